// round 4
// baseline (speedup 1.0000x reference)
#include <cuda_runtime.h>
#include <cstdint>
#include <math.h>

#define DDIM 128
#define BM 64
#define BN 128
#define KT 16
#define MAXROWS (1 << 17)
#define MAXK 4096

// -------- scratch (no allocations allowed) --------
__device__ int          g_idx[MAXROWS];
__device__ float        g_cnorm[MAXK];    // correctly-rounded fp32 of ||c_k||^2
__device__ unsigned int g_counts[MAXK];
__device__ float        g_sumsq;

// ---------------------------------------------------------------------------
// Kernel 1: c_norm_k = fp32(round(exact sum c^2)), zero accumulators.
// ---------------------------------------------------------------------------
__global__ __launch_bounds__(256) void prep_kernel(const float* __restrict__ cb, int K)
{
    int warp = threadIdx.x >> 5;
    int lane = threadIdx.x & 31;
    int code = blockIdx.x * 8 + warp;
    if (code < K) {
        const float* c = cb + (size_t)code * DDIM;
        double s = 0.0;
        #pragma unroll
        for (int j = 0; j < 4; j++) {
            double v = (double)c[lane + j * 32];
            s += v * v;                      // fp32*fp32 exact in fp64
        }
        #pragma unroll
        for (int o = 16; o > 0; o >>= 1) s += __shfl_down_sync(0xffffffffu, s, o);
        if (lane == 0) g_cnorm[code] = (float)s;   // correctly rounded
    }
    if (blockIdx.x == 0) {
        for (int i = threadIdx.x; i < K; i += blockDim.x) g_counts[i] = 0u;
        if (threadIdx.x == 0) g_sumsq = 0.f;
    }
}

// ---------------------------------------------------------------------------
// Kernel 2: fused GEMM + row-argmin with EXACT emulation of the reference's
// fp32 arithmetic:
//   dist_k = max( fl32( fl32(x_norm + c_norm_k) - 2*dot_k ), 0 ),  argmin,
//   first-index tie-break.
// Block: 64 rows x K codes (chunks of 128). 256 threads, 4x8 micro-tile.
// ---------------------------------------------------------------------------
__global__ __launch_bounds__(256) void argmin_kernel(
    const float* __restrict__ x, const float* __restrict__ cb,
    int nrows, int K)
{
    __shared__ float xs[BM][DDIM];                               // 32 KB
    __shared__ float sxn[BM];                                    // fp32 row norms
    __shared__ __align__(16) unsigned char cs_raw[KT * BN * 4];  // 8 KB
    float (*cs)[BN] = (float (*)[BN])cs_raw;
    float* rv = (float*)cs_raw;                                  // reduction overlay
    int*   ri = (int*)(cs_raw + BM * 16 * 4);

    const int tx = threadIdx.x & 15;   // code group
    const int ty = threadIdx.x >> 4;   // row group
    const int row0 = blockIdx.x * BM;

    // ---- load x tile (coalesced) ----
    #pragma unroll
    for (int it = 0; it < (BM * DDIM / 4) / 256; ++it) {
        int idx4 = threadIdx.x + it * 256;
        int r  = idx4 >> 5;
        int d4 = idx4 & 31;
        float4 v = make_float4(0.f, 0.f, 0.f, 0.f);
        int row = row0 + r;
        if (row < nrows) v = *(const float4*)(x + (size_t)row * DDIM + d4 * 4);
        *(float4*)(&xs[r][d4 * 4]) = v;
    }
    __syncthreads();

    // ---- x_norm per row: exact fp64 sum -> correctly-rounded fp32 ----
    if (threadIdx.x < BM) {
        const float* xr = xs[threadIdx.x];
        double s0 = 0.0, s1 = 0.0;
        #pragma unroll
        for (int d = 0; d < DDIM; d += 2) {
            double a = (double)xr[d], b = (double)xr[d + 1];
            s0 += a * a;
            s1 += b * b;
        }
        sxn[threadIdx.x] = (float)(s0 + s1);
    }
    __syncthreads();

    float bestv[4];
    int   besti[4];
    #pragma unroll
    for (int i = 0; i < 4; i++) { bestv[i] = 3.4e38f; besti[i] = 0; }

    for (int cb0 = 0; cb0 < K; cb0 += BN) {
        float acc[4][8];
        #pragma unroll
        for (int i = 0; i < 4; i++)
            #pragma unroll
            for (int j = 0; j < 8; j++) acc[i][j] = 0.f;

        for (int dc = 0; dc < DDIM; dc += KT) {
            #pragma unroll
            for (int it = 0; it < 2; ++it) {
                int idx4 = threadIdx.x + it * 256;
                int c  = idx4 >> 2;
                int d4 = idx4 & 3;
                float4 v = *(const float4*)(cb + (size_t)(cb0 + c) * DDIM + dc + d4 * 4);
                cs[d4 * 4 + 0][c] = v.x;
                cs[d4 * 4 + 1][c] = v.y;
                cs[d4 * 4 + 2][c] = v.z;
                cs[d4 * 4 + 3][c] = v.w;
            }
            __syncthreads();

            #pragma unroll
            for (int kk = 0; kk < KT; ++kk) {
                float a[4], b[8];
                #pragma unroll
                for (int i = 0; i < 4; i++) a[i] = xs[ty * 4 + i][dc + kk];
                #pragma unroll
                for (int j = 0; j < 8; j++) b[j] = cs[kk][j * 16 + tx];
                #pragma unroll
                for (int i = 0; i < 4; i++)
                    #pragma unroll
                    for (int j = 0; j < 8; j++)
                        acc[i][j] = __fmaf_rn(a[i], b[j], acc[i][j]);
            }
            __syncthreads();
        }

        // emulate reference rounding; codes ascend per thread -> strict <
        // keeps the lowest index within this thread's subset
        #pragma unroll
        for (int j = 0; j < 8; j++) {
            int code = cb0 + j * 16 + tx;
            float cn = g_cnorm[code];
            #pragma unroll
            for (int i = 0; i < 4; i++) {
                float t = __fadd_rn(sxn[ty * 4 + i], cn);        // fl(xn + cn)
                float d = __fmaf_rn(acc[i][j], -2.0f, t);        // fl(t - 2*dot)
                d = fmaxf(d, 0.0f);
                if (d < bestv[i]) { bestv[i] = d; besti[i] = code; }
            }
        }
    }

    // ---- cross-thread reduction (16 tx per row), first-index tie-break ----
    __syncthreads();
    #pragma unroll
    for (int i = 0; i < 4; i++) {
        int r = ty * 4 + i;
        rv[r * 16 + tx] = bestv[i];
        ri[r * 16 + tx] = besti[i];
    }
    __syncthreads();
    if (threadIdx.x < BM) {
        int r = threadIdx.x;
        float bv = rv[r * 16];
        int   bi = ri[r * 16];
        #pragma unroll
        for (int t = 1; t < 16; t++) {
            float v  = rv[r * 16 + t];
            int   id = ri[r * 16 + t];
            if (v < bv || (v == bv && id < bi)) { bv = v; bi = id; }
        }
        int row = row0 + r;
        if (row < nrows) g_idx[row] = bi;
    }
}

// ---------------------------------------------------------------------------
// Kernel 3: z_st = x + (z - x) elementwise fp32 (exact reference emulation),
// accumulate sum((z-x)^2) and histogram. Warp per row, 8 rows/block.
// ---------------------------------------------------------------------------
__global__ __launch_bounds__(256) void gather_kernel(
    const float* __restrict__ x, const float* __restrict__ cb,
    float* __restrict__ z, int nrows)
{
    __shared__ float ssum[8];
    int warp = threadIdx.x >> 5;
    int lane = threadIdx.x & 31;
    int row  = blockIdx.x * 8 + warp;

    float local = 0.f;
    if (row < nrows) {
        int k = g_idx[row];
        const float4* xr = (const float4*)(x + (size_t)row * DDIM);
        const float4* cr = (const float4*)(cb + (size_t)k * DDIM);
        float4*       zr = (float4*)(z + (size_t)row * DDIM);
        float4 xv = xr[lane];
        float4 cv = cr[lane];
        // diffs exactly as reference: d = fl(z - x)
        float dx = __fadd_rn(cv.x, -xv.x);
        float dy = __fadd_rn(cv.y, -xv.y);
        float dz = __fadd_rn(cv.z, -xv.z);
        float dw = __fadd_rn(cv.w, -xv.w);
        // z_st = fl(x + d)
        float4 ov;
        ov.x = __fadd_rn(xv.x, dx);
        ov.y = __fadd_rn(xv.y, dy);
        ov.z = __fadd_rn(xv.z, dz);
        ov.w = __fadd_rn(xv.w, dw);
        zr[lane] = ov;
        local = dx * dx + dy * dy + dz * dz + dw * dw;
        if (lane == 0) atomicAdd(&g_counts[k], 1u);
    }
    #pragma unroll
    for (int o = 16; o > 0; o >>= 1) local += __shfl_down_sync(0xffffffffu, local, o);
    if (lane == 0) ssum[warp] = local;
    __syncthreads();
    if (threadIdx.x == 0) {
        float s = 0.f;
        #pragma unroll
        for (int w = 0; w < 8; w++) s += ssum[w];
        atomicAdd(&g_sumsq, s);
    }
}

// ---------------------------------------------------------------------------
// Kernel 4: losses + perplexity scalars.
// ---------------------------------------------------------------------------
__global__ __launch_bounds__(256) void finalize_kernel(
    float* __restrict__ out, long long zoff, int nrows, int K)
{
    __shared__ float sh[256];
    int t = threadIdx.x;
    float term = 0.f;
    float inv_n = 1.f / (float)nrows;
    for (int i = t; i < K; i += 256) {
        float p = (float)g_counts[i] * inv_n;
        term += p * logf(p + 1e-10f);
    }
    sh[t] = term;
    __syncthreads();
    for (int s = 128; s > 0; s >>= 1) {
        if (t < s) sh[t] += sh[t + s];
        __syncthreads();
    }
    if (t == 0) {
        float q = g_sumsq / ((float)nrows * (float)DDIM);
        out[zoff + 0] = q;            // quantization_loss
        out[zoff + 1] = q;            // commitment_loss (same forward value)
        out[zoff + 2] = expf(-sh[0]); // perplexity
    }
}

// ---------------------------------------------------------------------------
extern "C" void kernel_launch(void* const* d_in, const int* in_sizes, int n_in,
                              void* d_out, int out_size)
{
    const float* x  = (const float*)d_in[0];
    const float* cb = (const float*)d_in[1];
    float* out = (float*)d_out;

    int nx    = in_sizes[0];
    int nrows = nx / DDIM;
    int K     = in_sizes[1] / DDIM;

    prep_kernel<<<(K + 7) / 8, 256>>>(cb, K);
    argmin_kernel<<<(nrows + BM - 1) / BM, 256>>>(x, cb, nrows, K);
    gather_kernel<<<(nrows + 7) / 8, 256>>>(x, cb, out, nrows);
    finalize_kernel<<<1, 256>>>(out, (long long)nx, nrows, K);
}

// round 8
// speedup vs baseline: 1.5863x; 1.5863x over previous
#include <cuda_runtime.h>
#include <cstdint>
#include <math.h>

#define DDIM    128
#define MAXROWS (1 << 17)
#define MAXK    2048

// ---------------- scratch (static device memory only) ----------------
__device__ int          g_idx[MAXROWS];
__device__ float        g_cnorm[MAXK];
__device__ unsigned int g_counts[MAXK];
__device__ float        g_sumsq;
// codebook split to tf32 hi/lo, pre-swizzled smem image (64-code chunks)
__device__ float        g_cbhi[MAXK * DDIM];
__device__ float        g_cblo[MAXK * DDIM];
// 16 argmin candidates per row (8 slots x best-2) from the approx pass
__device__ float        g_cand_v[MAXROWS * 16];
__device__ int          g_cand_i[MAXROWS * 16];

// ---------------- smem layout ----------------
#define OFF_A_HI  0        // 65536 : 4 panels x (128 rows x 128B)
#define OFF_A_LO  65536    // 65536
#define OFF_B     131072   // 65536 : 2 bufs x 32768
#define OFF_CNORM 196608   // 4096
#define OFF_XN    200704   // 512
#define OFF_XNP   201216   // 2048 : double[256]
#define SMEM_BYTES 203776

// ---------------- ptx helpers (family-portable only) ----------------
__device__ __forceinline__ uint32_t smem_u32(const void* p) {
    uint32_t a;
    asm("{ .reg .u64 t; cvta.to.shared.u64 t, %1; cvt.u32.u64 %0, t; }" : "=r"(a) : "l"(p));
    return a;
}
__device__ __forceinline__ uint32_t f2tf32(float v) {
    uint32_t r;
    asm("cvt.rna.tf32.f32 %0, %1;" : "=r"(r) : "f"(v));
    return r;
}
#define LDSM4(R, addr) \
    asm volatile("ldmatrix.sync.aligned.m8n8.x4.shared.b16 {%0,%1,%2,%3}, [%4];" \
        : "=r"((R)[0]), "=r"((R)[1]), "=r"((R)[2]), "=r"((R)[3]) : "r"(addr))
#define MMA_TF32(C, A, b0, b1) \
    asm volatile("mma.sync.aligned.m16n8k8.row.col.f32.tf32.tf32.f32 " \
        "{%0,%1,%2,%3}, {%4,%5,%6,%7}, {%8,%9}, {%0,%1,%2,%3};" \
        : "+f"((C)[0]), "+f"((C)[1]), "+f"((C)[2]), "+f"((C)[3]) \
        : "r"((A)[0]), "r"((A)[1]), "r"((A)[2]), "r"((A)[3]), "r"(b0), "r"(b1))
#define CP_ASYNC16(dst, src) \
    asm volatile("cp.async.cg.shared.global [%0], [%1], 16;" :: "r"(dst), "l"(src))
#define CP_COMMIT()  asm volatile("cp.async.commit_group;" ::: "memory")
#define CP_WAIT1()   asm volatile("cp.async.wait_group 1;" ::: "memory")
#define CP_WAIT0()   asm volatile("cp.async.wait_group 0;" ::: "memory")

// ---------------------------------------------------------------------------
// Kernel 1: split codebook into tf32 hi/lo (pre-swizzled layout), exact cnorm,
// zero accumulators. One block per code, 128 threads.
// ---------------------------------------------------------------------------
__global__ __launch_bounds__(128) void prep_kernel(const float* __restrict__ cb, int K)
{
    __shared__ double red[128];
    int k = blockIdx.x;
    int d = threadIdx.x;
    float v = cb[(size_t)k * DDIM + d];
    float hi = __uint_as_float(f2tf32(v));
    float lo = __uint_as_float(f2tf32(__fadd_rn(v, -hi)));

    int chunk = k >> 6, cloc = k & 63;
    int kc = d >> 5, e = d & 31;
    int col16 = e >> 2, w = e & 3;
    int off = cloc * 32 + (((col16 ^ (cloc & 7)) << 2) + w);
    int base = chunk * 8192 + kc * 2048;
    g_cbhi[base + off] = hi;
    g_cblo[base + off] = lo;

    red[d] = (double)v * (double)v;
    __syncthreads();
    for (int s = 64; s > 0; s >>= 1) {
        if (d < s) red[d] += red[d + s];
        __syncthreads();
    }
    if (d == 0) g_cnorm[k] = (float)red[0];

    if (k == 0) {
        for (int i = d; i < K; i += 128) g_counts[i] = 0u;
        if (d == 0) g_sumsq = 0.f;
    }
}

// ---------------------------------------------------------------------------
// Kernel 2: mma.sync tf32 3-term GEMM + rounding-emulated dist; emits 16
// (value,index) candidates per row (8 thread-slots x best-2, ascending-code).
// ---------------------------------------------------------------------------
__global__ __launch_bounds__(256, 1) void argmin_mma(
    const float* __restrict__ x, int nrows, int K)
{
    extern __shared__ char smc[];
    const uint32_t sb = smem_u32(smc);

    const int tid  = threadIdx.x;
    const int warp = tid >> 5;
    const int lane = tid & 31;
    const int row0 = blockIdx.x * 128;
    const int nsteps = (K >> 6) * 2;

    // ---- kick off first B fill ----
    {
        const char* src = (const char*)g_cbhi;
        #pragma unroll
        for (int i = 0; i < 8; i++) {
            int idx = tid + i * 256;
            CP_ASYNC16(sb + OFF_B + idx * 16, src + idx * 16);
        }
        CP_COMMIT();
    }

    // ---- stage A (tf32 hi/lo, swizzled) + fp64 norm partials ----
    {
        int r = tid >> 1, half = tid & 1;
        int row = row0 + r;
        const float4* xr = (const float4*)(x + (size_t)row * DDIM);
        double pn = 0.0;
        #pragma unroll
        for (int i = 0; i < 16; i++) {
            int e4 = half * 16 + i;
            float4 v = make_float4(0.f, 0.f, 0.f, 0.f);
            if (row < nrows) v = xr[e4];
            float4 hv, lv;
            hv.x = __uint_as_float(f2tf32(v.x));
            hv.y = __uint_as_float(f2tf32(v.y));
            hv.z = __uint_as_float(f2tf32(v.z));
            hv.w = __uint_as_float(f2tf32(v.w));
            lv.x = __uint_as_float(f2tf32(__fadd_rn(v.x, -hv.x)));
            lv.y = __uint_as_float(f2tf32(__fadd_rn(v.y, -hv.y)));
            lv.z = __uint_as_float(f2tf32(__fadd_rn(v.z, -hv.z)));
            lv.w = __uint_as_float(f2tf32(__fadd_rn(v.w, -hv.w)));
            pn += (double)v.x * v.x + (double)v.y * v.y
                + (double)v.z * v.z + (double)v.w * v.w;
            int kc = e4 >> 3, c16 = e4 & 7;
            int boff = kc * 16384 + r * 128 + ((c16 ^ (r & 7)) << 4);
            *(float4*)(smc + OFF_A_HI + boff) = hv;
            *(float4*)(smc + OFF_A_LO + boff) = lv;
        }
        ((double*)(smc + OFF_XNP))[tid] = pn;
    }
    for (int i = tid; i < K; i += 256)
        ((float*)(smc + OFF_CNORM))[i] = g_cnorm[i];
    __syncthreads();
    if (tid < 128) {
        const double* p = (const double*)(smc + OFF_XNP);
        ((float*)(smc + OFF_XN))[tid] = (float)(p[2 * tid] + p[2 * tid + 1]);
    }
    __syncthreads();

    // ---- per-lane constants ----
    const int warpM = warp >> 1, warpN = warp & 1;
    const int m0 = warpM * 32;
    const int g   = lane >> 2, tig = lane & 3;
    const int rsel = lane & 7;
    const int mselA = (lane >> 3) & 1, cselA = lane >> 4;
    const uint32_t rowOffA = (uint32_t)(m0 + mselA * 8 + rsel) * 128;
    const int cselB = (lane >> 3) & 1, nselB = lane >> 4;
    const uint32_t rowOffB = (uint32_t)(warpN * 32 + nselB * 8 + rsel) * 128;

    const float* xns = (const float*)(smc + OFF_XN);
    float xnr[4];
    #pragma unroll
    for (int mt = 0; mt < 2; mt++)
        #pragma unroll
        for (int h = 0; h < 2; h++)
            xnr[mt * 2 + h] = xns[m0 + mt * 16 + h * 8 + g];

    const float* cns = (const float*)(smc + OFF_CNORM);

    float acc[2][4][4];
    #pragma unroll
    for (int mt = 0; mt < 2; mt++)
        #pragma unroll
        for (int nt = 0; nt < 4; nt++)
            #pragma unroll
            for (int q = 0; q < 4; q++) acc[mt][nt][q] = 0.f;

    // best-2 per (mt,h) row-slot, ascending-code update preserves first-index
    float bv1[2][2], bv2[2][2];
    int   bi1[2][2], bi2[2][2];
    #pragma unroll
    for (int mt = 0; mt < 2; mt++)
        #pragma unroll
        for (int h = 0; h < 2; h++) {
            bv1[mt][h] = 3.4e38f; bi1[mt][h] = 0;
            bv2[mt][h] = 3.4e38f; bi2[mt][h] = 0;
        }

    for (int s = 0; s < nsteps; s++) {
        const int p = s & 1;
        if (s + 1 < nsteps) {
            int s2 = s + 1;
            const char* src = (const char*)(((s2 & 1) ? g_cblo : g_cbhi) + (s2 >> 1) * 8192);
            uint32_t dst = sb + OFF_B + (p ^ 1) * 32768;
            #pragma unroll
            for (int i = 0; i < 8; i++) {
                int idx = tid + i * 256;
                CP_ASYNC16(dst + idx * 16, src + idx * 16);
            }
            CP_COMMIT();
            CP_WAIT1();
        } else {
            CP_WAIT0();
        }
        __syncthreads();

        const uint32_t bbase = sb + OFF_B + p * 32768;
        const int scale = s & 1;

        if (scale == 0) {
            #pragma unroll
            for (int kstep = 0; kstep < 16; kstep++) {
                const int kc = kstep >> 2, j8 = kstep & 3;
                const uint32_t xa = (uint32_t)(((2 * j8 + cselA) ^ rsel) << 4);
                const uint32_t xb = (uint32_t)(((2 * j8 + cselB) ^ rsel) << 4);
                const uint32_t aph = sb + OFF_A_HI + kc * 16384 + rowOffA + xa;
                const uint32_t apl = sb + OFF_A_LO + kc * 16384 + rowOffA + xa;
                const uint32_t bp  = bbase + kc * 8192 + rowOffB + xb;
                uint32_t ah0[4], ah1[4], al0[4], al1[4], b0[4], b1[4];
                LDSM4(ah0, aph);
                LDSM4(ah1, aph + 2048);
                LDSM4(al0, apl);
                LDSM4(al1, apl + 2048);
                LDSM4(b0, bp);
                LDSM4(b1, bp + 2048);
                MMA_TF32(acc[0][0], ah0, b0[0], b0[1]);
                MMA_TF32(acc[0][1], ah0, b0[2], b0[3]);
                MMA_TF32(acc[0][2], ah0, b1[0], b1[1]);
                MMA_TF32(acc[0][3], ah0, b1[2], b1[3]);
                MMA_TF32(acc[1][0], ah1, b0[0], b0[1]);
                MMA_TF32(acc[1][1], ah1, b0[2], b0[3]);
                MMA_TF32(acc[1][2], ah1, b1[0], b1[1]);
                MMA_TF32(acc[1][3], ah1, b1[2], b1[3]);
                MMA_TF32(acc[0][0], al0, b0[0], b0[1]);
                MMA_TF32(acc[0][1], al0, b0[2], b0[3]);
                MMA_TF32(acc[0][2], al0, b1[0], b1[1]);
                MMA_TF32(acc[0][3], al0, b1[2], b1[3]);
                MMA_TF32(acc[1][0], al1, b0[0], b0[1]);
                MMA_TF32(acc[1][1], al1, b0[2], b0[3]);
                MMA_TF32(acc[1][2], al1, b1[0], b1[1]);
                MMA_TF32(acc[1][3], al1, b1[2], b1[3]);
            }
        } else {
            #pragma unroll
            for (int kstep = 0; kstep < 16; kstep++) {
                const int kc = kstep >> 2, j8 = kstep & 3;
                const uint32_t xa = (uint32_t)(((2 * j8 + cselA) ^ rsel) << 4);
                const uint32_t xb = (uint32_t)(((2 * j8 + cselB) ^ rsel) << 4);
                const uint32_t aph = sb + OFF_A_HI + kc * 16384 + rowOffA + xa;
                const uint32_t bp  = bbase + kc * 8192 + rowOffB + xb;
                uint32_t ah0[4], ah1[4], b0[4], b1[4];
                LDSM4(ah0, aph);
                LDSM4(ah1, aph + 2048);
                LDSM4(b0, bp);
                LDSM4(b1, bp + 2048);
                MMA_TF32(acc[0][0], ah0, b0[0], b0[1]);
                MMA_TF32(acc[0][1], ah0, b0[2], b0[3]);
                MMA_TF32(acc[0][2], ah0, b1[0], b1[1]);
                MMA_TF32(acc[0][3], ah0, b1[2], b1[3]);
                MMA_TF32(acc[1][0], ah1, b0[0], b0[1]);
                MMA_TF32(acc[1][1], ah1, b0[2], b0[3]);
                MMA_TF32(acc[1][2], ah1, b1[0], b1[1]);
                MMA_TF32(acc[1][3], ah1, b1[2], b1[3]);
            }

            // epilogue: rounding-emulated dist, best-2 tracking
            const int chunk = s >> 1;
            #pragma unroll
            for (int nt = 0; nt < 4; nt++) {
                const int cbse = chunk * 64 + warpN * 32 + nt * 8 + 2 * tig;
                const float cn0 = cns[cbse];
                const float cn1 = cns[cbse + 1];
                #pragma unroll
                for (int mt = 0; mt < 2; mt++) {
                    #pragma unroll
                    for (int h = 0; h < 2; h++) {
                        const float xn = xnr[mt * 2 + h];
                        float t0 = __fadd_rn(xn, cn0);
                        float d0 = __fmaf_rn(acc[mt][nt][h * 2 + 0], -2.0f, t0);
                        d0 = fmaxf(d0, 0.0f);
                        if (d0 < bv1[mt][h]) {
                            bv2[mt][h] = bv1[mt][h]; bi2[mt][h] = bi1[mt][h];
                            bv1[mt][h] = d0;         bi1[mt][h] = cbse;
                        } else if (d0 < bv2[mt][h]) {
                            bv2[mt][h] = d0;         bi2[mt][h] = cbse;
                        }
                        float t1 = __fadd_rn(xn, cn1);
                        float d1 = __fmaf_rn(acc[mt][nt][h * 2 + 1], -2.0f, t1);
                        d1 = fmaxf(d1, 0.0f);
                        if (d1 < bv1[mt][h]) {
                            bv2[mt][h] = bv1[mt][h]; bi2[mt][h] = bi1[mt][h];
                            bv1[mt][h] = d1;         bi1[mt][h] = cbse + 1;
                        } else if (d1 < bv2[mt][h]) {
                            bv2[mt][h] = d1;         bi2[mt][h] = cbse + 1;
                        }
                    }
                }
            }
            #pragma unroll
            for (int mt = 0; mt < 2; mt++)
                #pragma unroll
                for (int nt = 0; nt < 4; nt++)
                    #pragma unroll
                    for (int q = 0; q < 4; q++) acc[mt][nt][q] = 0.f;
        }
        __syncthreads();
    }

    // ---- dump 16 candidates per row ----
    {
        const int slot = warpN * 4 + tig;
        #pragma unroll
        for (int mt = 0; mt < 2; mt++)
            #pragma unroll
            for (int h = 0; h < 2; h++) {
                int r = m0 + mt * 16 + h * 8 + g;
                int row = row0 + r;
                if (row < nrows) {
                    size_t b = (size_t)row * 16 + slot * 2;
                    g_cand_v[b]     = bv1[mt][h];
                    g_cand_i[b]     = bi1[mt][h];
                    g_cand_v[b + 1] = bv2[mt][h];
                    g_cand_i[b + 1] = bi2[mt][h];
                }
            }
    }
}

// ---------------------------------------------------------------------------
// Kernel 3: rescore. One warp per row. Unique near-min candidate -> direct
// write. Else recompute dist with round-4's exact sequential FMA chain and
// first-index tie-break (proven zero-flip arithmetic). Single structured
// path for the whole warp (no divergent early return around warp syncs).
// ---------------------------------------------------------------------------
__global__ __launch_bounds__(256) void rescore_kernel(
    const float* __restrict__ x, const float* __restrict__ cb, int nrows)
{
    __shared__ float xs[8][DDIM];
    const int warp = threadIdx.x >> 5;
    const int lane = threadIdx.x & 31;
    const int row  = blockIdx.x * 8 + warp;
    const bool rok = (row < nrows);

    float v = 3.4e38f;
    int   ci = 0;
    if (rok && lane < 16) {
        v  = g_cand_v[(size_t)row * 16 + lane];
        ci = g_cand_i[(size_t)row * 16 + lane];
    }
    float vmin = v;
    #pragma unroll
    for (int o = 16; o > 0; o >>= 1)
        vmin = fminf(vmin, __shfl_xor_sync(0xffffffffu, vmin, o));

    const bool active = rok && (lane < 16) && (v <= vmin + 1e-4f);
    const unsigned int bal = __ballot_sync(0xffffffffu, active);
    const bool fast = (__popc(bal) == 1);

    if (fast) {
        if (active) g_idx[row] = ci;
    } else if (rok) {
        // slow path: exact rescore (round-4 arithmetic)
        const float4* xr = (const float4*)(x + (size_t)row * DDIM);
        float4 xv = xr[lane];
        *(float4*)(&xs[warp][lane * 4]) = xv;
        double pn = (double)xv.x * xv.x + (double)xv.y * xv.y
                  + (double)xv.z * xv.z + (double)xv.w * xv.w;
        #pragma unroll
        for (int o = 16; o > 0; o >>= 1)
            pn += __shfl_xor_sync(0xffffffffu, pn, o);
        const float xn = (float)pn;
        __syncwarp();

        float dd = 3.4e38f;
        int   ii = 0x7fffffff;
        if (active) {
            const float* cr = cb + (size_t)ci * DDIM;
            const float* xw = xs[warp];
            float acc = 0.f;
            #pragma unroll 16
            for (int d = 0; d < DDIM; d++)
                acc = __fmaf_rn(xw[d], __ldg(&cr[d]), acc);
            float t = __fadd_rn(xn, g_cnorm[ci]);
            dd = fmaxf(__fmaf_rn(acc, -2.0f, t), 0.0f);
            ii = ci;
        }
        #pragma unroll
        for (int o = 16; o > 0; o >>= 1) {
            float ov = __shfl_xor_sync(0xffffffffu, dd, o);
            int   oi = __shfl_xor_sync(0xffffffffu, ii, o);
            if (ov < dd || (ov == dd && oi < ii)) { dd = ov; ii = oi; }
        }
        if (lane == 0) g_idx[row] = ii;
    }
}

// ---------------------------------------------------------------------------
// Kernel 4: z_st = x + (z - x) (exact fp32 emulation), sum((z-x)^2), histogram.
// ---------------------------------------------------------------------------
__global__ __launch_bounds__(256) void gather_kernel(
    const float* __restrict__ x, const float* __restrict__ cb,
    float* __restrict__ z, int nrows)
{
    __shared__ float ssum[8];
    int warp = threadIdx.x >> 5;
    int lane = threadIdx.x & 31;
    int row  = blockIdx.x * 8 + warp;

    float local = 0.f;
    if (row < nrows) {
        int k = g_idx[row];
        const float4* xr = (const float4*)(x + (size_t)row * DDIM);
        const float4* cr = (const float4*)(cb + (size_t)k * DDIM);
        float4*       zr = (float4*)(z + (size_t)row * DDIM);
        float4 xv = xr[lane];
        float4 cv = cr[lane];
        float dx = __fadd_rn(cv.x, -xv.x);
        float dy = __fadd_rn(cv.y, -xv.y);
        float dz = __fadd_rn(cv.z, -xv.z);
        float dw = __fadd_rn(cv.w, -xv.w);
        float4 ov;
        ov.x = __fadd_rn(xv.x, dx);
        ov.y = __fadd_rn(xv.y, dy);
        ov.z = __fadd_rn(xv.z, dz);
        ov.w = __fadd_rn(xv.w, dw);
        zr[lane] = ov;
        local = dx * dx + dy * dy + dz * dz + dw * dw;
        if (lane == 0) atomicAdd(&g_counts[k], 1u);
    }
    #pragma unroll
    for (int o = 16; o > 0; o >>= 1) local += __shfl_down_sync(0xffffffffu, local, o);
    if (lane == 0) ssum[warp] = local;
    __syncthreads();
    if (threadIdx.x == 0) {
        float s = 0.f;
        #pragma unroll
        for (int w = 0; w < 8; w++) s += ssum[w];
        atomicAdd(&g_sumsq, s);
    }
}

// ---------------------------------------------------------------------------
// Kernel 5: losses + perplexity scalars.
// ---------------------------------------------------------------------------
__global__ __launch_bounds__(256) void finalize_kernel(
    float* __restrict__ out, long long zoff, int nrows, int K)
{
    __shared__ float sh[256];
    int t = threadIdx.x;
    float term = 0.f;
    float inv_n = 1.f / (float)nrows;
    for (int i = t; i < K; i += 256) {
        float p = (float)g_counts[i] * inv_n;
        term += p * logf(p + 1e-10f);
    }
    sh[t] = term;
    __syncthreads();
    for (int s = 128; s > 0; s >>= 1) {
        if (t < s) sh[t] += sh[t + s];
        __syncthreads();
    }
    if (t == 0) {
        float q = g_sumsq / ((float)nrows * (float)DDIM);
        out[zoff + 0] = q;
        out[zoff + 1] = q;
        out[zoff + 2] = expf(-sh[0]);
    }
}

// ---------------------------------------------------------------------------
extern "C" void kernel_launch(void* const* d_in, const int* in_sizes, int n_in,
                              void* d_out, int out_size)
{
    const float* x  = (const float*)d_in[0];
    const float* cb = (const float*)d_in[1];
    float* out = (float*)d_out;

    int nx    = in_sizes[0];
    int nrows = nx / DDIM;
    int K     = in_sizes[1] / DDIM;

    cudaFuncSetAttribute(argmin_mma, cudaFuncAttributeMaxDynamicSharedMemorySize, SMEM_BYTES);

    prep_kernel<<<K, 128>>>(cb, K);
    argmin_mma<<<(nrows + 127) / 128, 256, SMEM_BYTES>>>(x, nrows, K);
    rescore_kernel<<<(nrows + 7) / 8, 256>>>(x, cb, nrows);
    gather_kernel<<<(nrows + 7) / 8, 256>>>(x, cb, out, nrows);
    finalize_kernel<<<1, 256>>>(out, (long long)nx, nrows, K);
}

// round 9
// speedup vs baseline: 2.6370x; 1.6624x over previous
#include <cuda_runtime.h>
#include <cstdint>
#include <math.h>

#define DDIM    128
#define MAXROWS (1 << 17)
#define MAXK    2048
#define MARGIN  2e-4f

// ---------------- scratch (static device memory only) ----------------
__device__ int          g_idx[MAXROWS];
__device__ float        g_cnorm[MAXK];
__device__ unsigned int g_counts[MAXK];
__device__ float        g_sumsq;
// codebook tf32-hi, pre-swizzled smem image (64-code chunks of 32KB)
__device__ float        g_cbhi[MAXK * DDIM];
// 16 argmin candidates per row (8 slots x best-2) from the approx pass
__device__ float        g_cand_v[MAXROWS * 16];
__device__ int          g_cand_i[MAXROWS * 16];

// ---------------- smem layout ----------------
#define OFF_A_HI  0        // 65536 : 4 panels x (128 rows x 128B)
#define OFF_B     65536    // 65536 : 2 bufs x 32768 (one 64-code chunk)
#define OFF_CNORM 131072   // 4096
#define OFF_XN    135168   // 512
#define OFF_XNP   135680   // 2048 : double[256]
#define SMEM_BYTES 137728

// ---------------- ptx helpers (family-portable only) ----------------
__device__ __forceinline__ uint32_t smem_u32(const void* p) {
    uint32_t a;
    asm("{ .reg .u64 t; cvta.to.shared.u64 t, %1; cvt.u32.u64 %0, t; }" : "=r"(a) : "l"(p));
    return a;
}
__device__ __forceinline__ uint32_t f2tf32(float v) {
    uint32_t r;
    asm("cvt.rna.tf32.f32 %0, %1;" : "=r"(r) : "f"(v));
    return r;
}
#define LDSM4(R, addr) \
    asm volatile("ldmatrix.sync.aligned.m8n8.x4.shared.b16 {%0,%1,%2,%3}, [%4];" \
        : "=r"((R)[0]), "=r"((R)[1]), "=r"((R)[2]), "=r"((R)[3]) : "r"(addr))
#define MMA_TF32(C, A, b0, b1) \
    asm volatile("mma.sync.aligned.m16n8k8.row.col.f32.tf32.tf32.f32 " \
        "{%0,%1,%2,%3}, {%4,%5,%6,%7}, {%8,%9}, {%0,%1,%2,%3};" \
        : "+f"((C)[0]), "+f"((C)[1]), "+f"((C)[2]), "+f"((C)[3]) \
        : "r"((A)[0]), "r"((A)[1]), "r"((A)[2]), "r"((A)[3]), "r"(b0), "r"(b1))
#define CP_ASYNC16(dst, src) \
    asm volatile("cp.async.cg.shared.global [%0], [%1], 16;" :: "r"(dst), "l"(src))
#define CP_COMMIT()  asm volatile("cp.async.commit_group;" ::: "memory")
#define CP_WAIT1()   asm volatile("cp.async.wait_group 1;" ::: "memory")
#define CP_WAIT0()   asm volatile("cp.async.wait_group 0;" ::: "memory")

// ---------------------------------------------------------------------------
// Kernel 1: codebook -> tf32 hi (pre-swizzled layout), exact fp64 cnorm,
// zero accumulators. One block per code, 128 threads.
// ---------------------------------------------------------------------------
__global__ __launch_bounds__(128) void prep_kernel(const float* __restrict__ cb, int K)
{
    __shared__ double red[128];
    int k = blockIdx.x;
    int d = threadIdx.x;
    float v = cb[(size_t)k * DDIM + d];
    float hi = __uint_as_float(f2tf32(v));

    int chunk = k >> 6, cloc = k & 63;
    int kc = d >> 5, e = d & 31;
    int col16 = e >> 2, w = e & 3;
    int off = cloc * 32 + (((col16 ^ (cloc & 7)) << 2) + w);
    g_cbhi[chunk * 8192 + kc * 2048 + off] = hi;

    red[d] = (double)v * (double)v;
    __syncthreads();
    for (int s = 64; s > 0; s >>= 1) {
        if (d < s) red[d] += red[d + s];
        __syncthreads();
    }
    if (d == 0) g_cnorm[k] = (float)red[0];

    if (k == 0) {
        for (int i = d; i < K; i += 128) g_counts[i] = 0u;
        if (d == 0) g_sumsq = 0.f;
    }
}

// ---------------------------------------------------------------------------
// Kernel 2: single-pass tf32 mma.sync GEMM + rounding-emulated dist; emits
// 16 (value,index) candidates per row (8 slots x best-2, ascending-code).
// ---------------------------------------------------------------------------
__global__ __launch_bounds__(256, 1) void argmin_mma(
    const float* __restrict__ x, int nrows, int K)
{
    extern __shared__ char smc[];
    const uint32_t sb = smem_u32(smc);

    const int tid  = threadIdx.x;
    const int warp = tid >> 5;
    const int lane = tid & 31;
    const int row0 = blockIdx.x * 128;
    const int nsteps = K >> 6;                 // 64-code chunks

    // ---- kick off first B fill (chunk 0) ----
    {
        const char* src = (const char*)g_cbhi;
        #pragma unroll
        for (int i = 0; i < 8; i++) {
            int idx = tid + i * 256;
            CP_ASYNC16(sb + OFF_B + idx * 16, src + idx * 16);
        }
        CP_COMMIT();
    }

    // ---- stage A (tf32 hi, swizzled) + fp64 norm partials ----
    {
        int r = tid >> 1, half = tid & 1;
        int row = row0 + r;
        const float4* xr = (const float4*)(x + (size_t)row * DDIM);
        double pn = 0.0;
        #pragma unroll
        for (int i = 0; i < 16; i++) {
            int e4 = half * 16 + i;
            float4 v = make_float4(0.f, 0.f, 0.f, 0.f);
            if (row < nrows) v = xr[e4];
            float4 hv;
            hv.x = __uint_as_float(f2tf32(v.x));
            hv.y = __uint_as_float(f2tf32(v.y));
            hv.z = __uint_as_float(f2tf32(v.z));
            hv.w = __uint_as_float(f2tf32(v.w));
            pn += (double)v.x * v.x + (double)v.y * v.y
                + (double)v.z * v.z + (double)v.w * v.w;
            int kc = e4 >> 3, c16 = e4 & 7;
            int boff = kc * 16384 + r * 128 + ((c16 ^ (r & 7)) << 4);
            *(float4*)(smc + OFF_A_HI + boff) = hv;
        }
        ((double*)(smc + OFF_XNP))[tid] = pn;
    }
    for (int i = tid; i < K; i += 256)
        ((float*)(smc + OFF_CNORM))[i] = g_cnorm[i];
    __syncthreads();
    if (tid < 128) {
        const double* p = (const double*)(smc + OFF_XNP);
        ((float*)(smc + OFF_XN))[tid] = (float)(p[2 * tid] + p[2 * tid + 1]);
    }
    __syncthreads();

    // ---- per-lane constants ----
    const int warpM = warp >> 1, warpN = warp & 1;
    const int m0 = warpM * 32;
    const int g   = lane >> 2, tig = lane & 3;
    const int rsel = lane & 7;
    const int mselA = (lane >> 3) & 1, cselA = lane >> 4;
    const uint32_t rowOffA = (uint32_t)(m0 + mselA * 8 + rsel) * 128;
    const int cselB = (lane >> 3) & 1, nselB = lane >> 4;
    const uint32_t rowOffB = (uint32_t)(warpN * 32 + nselB * 8 + rsel) * 128;

    const float* xns = (const float*)(smc + OFF_XN);
    float xnr[4];
    #pragma unroll
    for (int mt = 0; mt < 2; mt++)
        #pragma unroll
        for (int h = 0; h < 2; h++)
            xnr[mt * 2 + h] = xns[m0 + mt * 16 + h * 8 + g];

    const float* cns = (const float*)(smc + OFF_CNORM);

    float acc[2][4][4];
    #pragma unroll
    for (int mt = 0; mt < 2; mt++)
        #pragma unroll
        for (int nt = 0; nt < 4; nt++)
            #pragma unroll
            for (int q = 0; q < 4; q++) acc[mt][nt][q] = 0.f;

    // best-2 per (mt,h) row-slot, ascending-code update preserves first-index
    float bv1[2][2], bv2[2][2];
    int   bi1[2][2], bi2[2][2];
    #pragma unroll
    for (int mt = 0; mt < 2; mt++)
        #pragma unroll
        for (int h = 0; h < 2; h++) {
            bv1[mt][h] = 3.4e38f; bi1[mt][h] = 0;
            bv2[mt][h] = 3.4e38f; bi2[mt][h] = 0;
        }

    for (int s = 0; s < nsteps; s++) {
        const int p = s & 1;
        if (s + 1 < nsteps) {
            const char* src = (const char*)(g_cbhi + (size_t)(s + 1) * 8192);
            uint32_t dst = sb + OFF_B + (p ^ 1) * 32768;
            #pragma unroll
            for (int i = 0; i < 8; i++) {
                int idx = tid + i * 256;
                CP_ASYNC16(dst + idx * 16, src + idx * 16);
            }
            CP_COMMIT();
            CP_WAIT1();
        } else {
            CP_WAIT0();
        }
        __syncthreads();

        const uint32_t bbase = sb + OFF_B + p * 32768;

        #pragma unroll
        for (int kstep = 0; kstep < 16; kstep++) {
            const int kc = kstep >> 2, j8 = kstep & 3;
            const uint32_t xa = (uint32_t)(((2 * j8 + cselA) ^ rsel) << 4);
            const uint32_t xb = (uint32_t)(((2 * j8 + cselB) ^ rsel) << 4);
            const uint32_t aph = sb + OFF_A_HI + kc * 16384 + rowOffA + xa;
            const uint32_t bp  = bbase + kc * 8192 + rowOffB + xb;
            uint32_t ah0[4], ah1[4], b0[4], b1[4];
            LDSM4(ah0, aph);
            LDSM4(ah1, aph + 2048);
            LDSM4(b0, bp);
            LDSM4(b1, bp + 2048);
            MMA_TF32(acc[0][0], ah0, b0[0], b0[1]);
            MMA_TF32(acc[0][1], ah0, b0[2], b0[3]);
            MMA_TF32(acc[0][2], ah0, b1[0], b1[1]);
            MMA_TF32(acc[0][3], ah0, b1[2], b1[3]);
            MMA_TF32(acc[1][0], ah1, b0[0], b0[1]);
            MMA_TF32(acc[1][1], ah1, b0[2], b0[3]);
            MMA_TF32(acc[1][2], ah1, b1[0], b1[1]);
            MMA_TF32(acc[1][3], ah1, b1[2], b1[3]);
        }

        // epilogue: rounding-emulated dist, best-2 tracking (codes ascend)
        #pragma unroll
        for (int nt = 0; nt < 4; nt++) {
            const int cbse = s * 64 + warpN * 32 + nt * 8 + 2 * tig;
            const float cn0 = cns[cbse];
            const float cn1 = cns[cbse + 1];
            #pragma unroll
            for (int mt = 0; mt < 2; mt++) {
                #pragma unroll
                for (int h = 0; h < 2; h++) {
                    const float xn = xnr[mt * 2 + h];
                    float t0 = __fadd_rn(xn, cn0);
                    float d0 = __fmaf_rn(acc[mt][nt][h * 2 + 0], -2.0f, t0);
                    d0 = fmaxf(d0, 0.0f);
                    if (d0 < bv1[mt][h]) {
                        bv2[mt][h] = bv1[mt][h]; bi2[mt][h] = bi1[mt][h];
                        bv1[mt][h] = d0;         bi1[mt][h] = cbse;
                    } else if (d0 < bv2[mt][h]) {
                        bv2[mt][h] = d0;         bi2[mt][h] = cbse;
                    }
                    float t1 = __fadd_rn(xn, cn1);
                    float d1 = __fmaf_rn(acc[mt][nt][h * 2 + 1], -2.0f, t1);
                    d1 = fmaxf(d1, 0.0f);
                    if (d1 < bv1[mt][h]) {
                        bv2[mt][h] = bv1[mt][h]; bi2[mt][h] = bi1[mt][h];
                        bv1[mt][h] = d1;         bi1[mt][h] = cbse + 1;
                    } else if (d1 < bv2[mt][h]) {
                        bv2[mt][h] = d1;         bi2[mt][h] = cbse + 1;
                    }
                }
            }
        }
        #pragma unroll
        for (int mt = 0; mt < 2; mt++)
            #pragma unroll
            for (int nt = 0; nt < 4; nt++)
                #pragma unroll
                for (int q = 0; q < 4; q++) acc[mt][nt][q] = 0.f;
        __syncthreads();
    }

    // ---- dump 16 candidates per row ----
    {
        const int slot = warpN * 4 + tig;
        #pragma unroll
        for (int mt = 0; mt < 2; mt++)
            #pragma unroll
            for (int h = 0; h < 2; h++) {
                int r = m0 + mt * 16 + h * 8 + g;
                int row = row0 + r;
                if (row < nrows) {
                    size_t b = (size_t)row * 16 + slot * 2;
                    g_cand_v[b]     = bv1[mt][h];
                    g_cand_i[b]     = bi1[mt][h];
                    g_cand_v[b + 1] = bv2[mt][h];
                    g_cand_i[b + 1] = bi2[mt][h];
                }
            }
    }
}

// ---------------------------------------------------------------------------
// Kernel 3: fused rescore + gather. One warp per row.
// Resolve winner (unique near-min -> direct; else exact round-4 FMA-chain
// rescore with first-index tie-break), then z_st = x + (z - x), sum((z-x)^2),
// histogram — all on the one x-row load.
// ---------------------------------------------------------------------------
__global__ __launch_bounds__(256) void rescore_gather_kernel(
    const float* __restrict__ x, const float* __restrict__ cb,
    float* __restrict__ z, int nrows)
{
    __shared__ float xs[8][DDIM];
    __shared__ float ssum[8];
    const int warp = threadIdx.x >> 5;
    const int lane = threadIdx.x & 31;
    const int row  = blockIdx.x * 8 + warp;
    const bool rok = (row < nrows);

    // candidate scan
    float v = 3.4e38f;
    int   ci = 0;
    if (rok && lane < 16) {
        v  = g_cand_v[(size_t)row * 16 + lane];
        ci = g_cand_i[(size_t)row * 16 + lane];
    }
    float vmin = v;
    #pragma unroll
    for (int o = 16; o > 0; o >>= 1)
        vmin = fminf(vmin, __shfl_xor_sync(0xffffffffu, vmin, o));

    const bool active = rok && (lane < 16) && (v <= vmin + MARGIN);
    const unsigned int bal = __ballot_sync(0xffffffffu, active);

    // x row (always needed for gather)
    float4 xv = make_float4(0.f, 0.f, 0.f, 0.f);
    if (rok) xv = ((const float4*)(x + (size_t)row * DDIM))[lane];

    int ii = 0;
    if (__popc(bal) == 1) {
        int src = __ffs(bal) - 1;
        ii = __shfl_sync(0xffffffffu, ci, src);
    } else {
        // slow path: exact rescore (round-4 arithmetic)
        *(float4*)(&xs[warp][lane * 4]) = xv;
        double pn = (double)xv.x * xv.x + (double)xv.y * xv.y
                  + (double)xv.z * xv.z + (double)xv.w * xv.w;
        #pragma unroll
        for (int o = 16; o > 0; o >>= 1)
            pn += __shfl_xor_sync(0xffffffffu, pn, o);
        const float xn = (float)pn;
        __syncwarp();

        float dd = 3.4e38f;
        int   di = 0x7fffffff;
        if (active) {
            const float* cr = cb + (size_t)ci * DDIM;
            const float* xw = xs[warp];
            float acc = 0.f;
            #pragma unroll 16
            for (int d = 0; d < DDIM; d++)
                acc = __fmaf_rn(xw[d], __ldg(&cr[d]), acc);
            float t = __fadd_rn(xn, g_cnorm[ci]);
            dd = fmaxf(__fmaf_rn(acc, -2.0f, t), 0.0f);
            di = ci;
        }
        #pragma unroll
        for (int o = 16; o > 0; o >>= 1) {
            float ov = __shfl_xor_sync(0xffffffffu, dd, o);
            int   oi = __shfl_xor_sync(0xffffffffu, di, o);
            if (ov < dd || (ov == dd && oi < di)) { dd = ov; di = oi; }
        }
        ii = di;
    }

    // gather + z_st + losses
    float local = 0.f;
    if (rok) {
        const float4* cr = (const float4*)(cb + (size_t)ii * DDIM);
        float4*       zr = (float4*)(z + (size_t)row * DDIM);
        float4 cv = cr[lane];
        float dx = __fadd_rn(cv.x, -xv.x);
        float dy = __fadd_rn(cv.y, -xv.y);
        float dz = __fadd_rn(cv.z, -xv.z);
        float dw = __fadd_rn(cv.w, -xv.w);
        float4 ov;
        ov.x = __fadd_rn(xv.x, dx);
        ov.y = __fadd_rn(xv.y, dy);
        ov.z = __fadd_rn(xv.z, dz);
        ov.w = __fadd_rn(xv.w, dw);
        zr[lane] = ov;
        local = dx * dx + dy * dy + dz * dz + dw * dw;
        if (lane == 0) atomicAdd(&g_counts[ii], 1u);
    }
    #pragma unroll
    for (int o = 16; o > 0; o >>= 1) local += __shfl_down_sync(0xffffffffu, local, o);
    if (lane == 0) ssum[warp] = local;
    __syncthreads();
    if (threadIdx.x == 0) {
        float s = 0.f;
        #pragma unroll
        for (int w = 0; w < 8; w++) s += ssum[w];
        atomicAdd(&g_sumsq, s);
    }
}

// ---------------------------------------------------------------------------
// Kernel 4: losses + perplexity scalars.
// ---------------------------------------------------------------------------
__global__ __launch_bounds__(256) void finalize_kernel(
    float* __restrict__ out, long long zoff, int nrows, int K)
{
    __shared__ float sh[256];
    int t = threadIdx.x;
    float term = 0.f;
    float inv_n = 1.f / (float)nrows;
    for (int i = t; i < K; i += 256) {
        float p = (float)g_counts[i] * inv_n;
        term += p * logf(p + 1e-10f);
    }
    sh[t] = term;
    __syncthreads();
    for (int s = 128; s > 0; s >>= 1) {
        if (t < s) sh[t] += sh[t + s];
        __syncthreads();
    }
    if (t == 0) {
        float q = g_sumsq / ((float)nrows * (float)DDIM);
        out[zoff + 0] = q;
        out[zoff + 1] = q;
        out[zoff + 2] = expf(-sh[0]);
    }
}

// ---------------------------------------------------------------------------
extern "C" void kernel_launch(void* const* d_in, const int* in_sizes, int n_in,
                              void* d_out, int out_size)
{
    const float* x  = (const float*)d_in[0];
    const float* cb = (const float*)d_in[1];
    float* out = (float*)d_out;

    int nx    = in_sizes[0];
    int nrows = nx / DDIM;
    int K     = in_sizes[1] / DDIM;

    cudaFuncSetAttribute(argmin_mma, cudaFuncAttributeMaxDynamicSharedMemorySize, SMEM_BYTES);

    prep_kernel<<<K, 128>>>(cb, K);
    argmin_mma<<<(nrows + 127) / 128, 256, SMEM_BYTES>>>(x, nrows, K);
    rescore_gather_kernel<<<(nrows + 7) / 8, 256>>>(x, cb, out, nrows);
    finalize_kernel<<<1, 256>>>(out, (long long)nx, nrows, K);
}

// round 11
// speedup vs baseline: 2.6463x; 1.0035x over previous
#include <cuda_runtime.h>
#include <cstdint>
#include <math.h>

#define DDIM    128
#define MAXROWS (1 << 17)
#define MAXK    2048
#define MARGIN  2e-4f

// ---------------- scratch (static device memory only) ----------------
__device__ int          g_idx[MAXROWS];
__device__ float        g_cnorm[MAXK];
__device__ unsigned int g_counts[MAXK];
__device__ float        g_sumsq;
// codebook tf32-hi, pre-swizzled smem image (128-code chunks of 64KB:
// 4 k-panels x [128 rows x 128B], rows XOR-swizzled)
__device__ float        g_cbhi[MAXK * DDIM];
// 16 argmin candidates per row (8 slots x best-2) from the approx pass
__device__ float        g_cand_v[MAXROWS * 16];
__device__ int          g_cand_i[MAXROWS * 16];

// ---------------- smem layout ----------------
#define OFF_A_HI  0        // 65536 : 4 panels x (128 rows x 128B)
#define OFF_B     65536    // 131072: 2 bufs x 65536 (one 128-code chunk)
#define OFF_CNORM 196608   // 4096
#define OFF_XN    200704   // 512
#define OFF_XNP   201216   // 2048 : double[256]
#define SMEM_BYTES 203264

// ---------------- ptx helpers (family-portable only) ----------------
__device__ __forceinline__ uint32_t smem_u32(const void* p) {
    uint32_t a;
    asm("{ .reg .u64 t; cvta.to.shared.u64 t, %1; cvt.u32.u64 %0, t; }" : "=r"(a) : "l"(p));
    return a;
}
__device__ __forceinline__ uint32_t f2tf32(float v) {
    uint32_t r;
    asm("cvt.rna.tf32.f32 %0, %1;" : "=r"(r) : "f"(v));
    return r;
}
#define LDSM4(R, addr) \
    asm volatile("ldmatrix.sync.aligned.m8n8.x4.shared.b16 {%0,%1,%2,%3}, [%4];" \
        : "=r"((R)[0]), "=r"((R)[1]), "=r"((R)[2]), "=r"((R)[3]) : "r"(addr))
#define MMA_TF32(C, A, b0, b1) \
    asm volatile("mma.sync.aligned.m16n8k8.row.col.f32.tf32.tf32.f32 " \
        "{%0,%1,%2,%3}, {%4,%5,%6,%7}, {%8,%9}, {%0,%1,%2,%3};" \
        : "+f"((C)[0]), "+f"((C)[1]), "+f"((C)[2]), "+f"((C)[3]) \
        : "r"((A)[0]), "r"((A)[1]), "r"((A)[2]), "r"((A)[3]), "r"(b0), "r"(b1))
#define CP_ASYNC16(dst, src) \
    asm volatile("cp.async.cg.shared.global [%0], [%1], 16;" :: "r"(dst), "l"(src))
#define CP_COMMIT()  asm volatile("cp.async.commit_group;" ::: "memory")
#define CP_WAIT1()   asm volatile("cp.async.wait_group 1;" ::: "memory")
#define CP_WAIT0()   asm volatile("cp.async.wait_group 0;" ::: "memory")

// ---------------------------------------------------------------------------
// Kernel 1: codebook -> tf32 hi (pre-swizzled 128-code-chunk layout), exact
// fp64 cnorm, zero accumulators. One block per code, 128 threads.
// ---------------------------------------------------------------------------
__global__ __launch_bounds__(128) void prep_kernel(const float* __restrict__ cb, int K)
{
    __shared__ double red[128];
    int k = blockIdx.x;
    int d = threadIdx.x;
    float v = cb[(size_t)k * DDIM + d];
    float hi = __uint_as_float(f2tf32(v));

    int chunk = k >> 7, cloc = k & 127;
    int kc = d >> 5, e = d & 31;
    int col16 = e >> 2, w = e & 3;
    int off = cloc * 32 + (((col16 ^ (cloc & 7)) << 2) + w);
    g_cbhi[chunk * 16384 + kc * 4096 + off] = hi;

    red[d] = (double)v * (double)v;
    __syncthreads();
    for (int s = 64; s > 0; s >>= 1) {
        if (d < s) red[d] += red[d + s];
        __syncthreads();
    }
    if (d == 0) g_cnorm[k] = (float)red[0];

    if (k == 0) {
        for (int i = d; i < K; i += 128) g_counts[i] = 0u;
        if (d == 0) g_sumsq = 0.f;
    }
}

// ---------------------------------------------------------------------------
// Kernel 2: single-pass tf32 mma.sync GEMM, warp tile m32 x n64, 128-code
// chunks; rounding-emulated dist; emits 16 candidates/row (8 slots x best-2).
// ---------------------------------------------------------------------------
__global__ __launch_bounds__(256, 1) void argmin_mma(
    const float* __restrict__ x, int nrows, int K)
{
    extern __shared__ char smc[];
    const uint32_t sb = smem_u32(smc);

    const int tid  = threadIdx.x;
    const int warp = tid >> 5;
    const int lane = tid & 31;
    const int row0 = blockIdx.x * 128;
    const int nsteps = K >> 7;                 // 128-code chunks

    // ---- kick off first B fill (chunk 0, 64KB) ----
    {
        const char* src = (const char*)g_cbhi;
        #pragma unroll
        for (int i = 0; i < 16; i++) {
            int idx = tid + i * 256;           // 4096 float4
            CP_ASYNC16(sb + OFF_B + idx * 16, src + idx * 16);
        }
        CP_COMMIT();
    }

    // ---- stage A (tf32 hi, swizzled) + fp64 norm partials ----
    {
        int r = tid >> 1, half = tid & 1;
        int row = row0 + r;
        const float4* xr = (const float4*)(x + (size_t)row * DDIM);
        double pn = 0.0;
        #pragma unroll
        for (int i = 0; i < 16; i++) {
            int e4 = half * 16 + i;
            float4 v = make_float4(0.f, 0.f, 0.f, 0.f);
            if (row < nrows) v = xr[e4];
            float4 hv;
            hv.x = __uint_as_float(f2tf32(v.x));
            hv.y = __uint_as_float(f2tf32(v.y));
            hv.z = __uint_as_float(f2tf32(v.z));
            hv.w = __uint_as_float(f2tf32(v.w));
            pn += (double)v.x * v.x + (double)v.y * v.y
                + (double)v.z * v.z + (double)v.w * v.w;
            int kc = e4 >> 3, c16 = e4 & 7;
            int boff = kc * 16384 + r * 128 + ((c16 ^ (r & 7)) << 4);
            *(float4*)(smc + OFF_A_HI + boff) = hv;
        }
        ((double*)(smc + OFF_XNP))[tid] = pn;
    }
    for (int i = tid; i < K; i += 256)
        ((float*)(smc + OFF_CNORM))[i] = g_cnorm[i];
    __syncthreads();
    if (tid < 128) {
        const double* p = (const double*)(smc + OFF_XNP);
        ((float*)(smc + OFF_XN))[tid] = (float)(p[2 * tid] + p[2 * tid + 1]);
    }
    __syncthreads();

    // ---- per-lane constants ----
    const int warpM = warp >> 1, warpN = warp & 1;   // 4M x 2N
    const int m0 = warpM * 32;
    const int g   = lane >> 2, tig = lane & 3;
    const int rsel = lane & 7;
    const int mselA = (lane >> 3) & 1, cselA = lane >> 4;
    const uint32_t rowOffA = (uint32_t)(m0 + mselA * 8 + rsel) * 128;
    const int cselB = (lane >> 3) & 1, nselB = lane >> 4;
    const uint32_t rowOffB = (uint32_t)(warpN * 64 + nselB * 8 + rsel) * 128;

    const float* xns = (const float*)(smc + OFF_XN);
    float xnr[4];
    #pragma unroll
    for (int mt = 0; mt < 2; mt++)
        #pragma unroll
        for (int h = 0; h < 2; h++)
            xnr[mt * 2 + h] = xns[m0 + mt * 16 + h * 8 + g];

    const float* cns = (const float*)(smc + OFF_CNORM);

    float acc[2][8][4];
    #pragma unroll
    for (int mt = 0; mt < 2; mt++)
        #pragma unroll
        for (int nt = 0; nt < 8; nt++)
            #pragma unroll
            for (int q = 0; q < 4; q++) acc[mt][nt][q] = 0.f;

    // best-2 per (mt,h) row-slot, ascending-code update preserves first-index
    float bv1[2][2], bv2[2][2];
    int   bi1[2][2], bi2[2][2];
    #pragma unroll
    for (int mt = 0; mt < 2; mt++)
        #pragma unroll
        for (int h = 0; h < 2; h++) {
            bv1[mt][h] = 3.4e38f; bi1[mt][h] = 0;
            bv2[mt][h] = 3.4e38f; bi2[mt][h] = 0;
        }

    for (int s = 0; s < nsteps; s++) {
        const int p = s & 1;
        if (s + 1 < nsteps) {
            const char* src = (const char*)(g_cbhi + (size_t)(s + 1) * 16384);
            uint32_t dst = sb + OFF_B + (p ^ 1) * 65536;
            #pragma unroll
            for (int i = 0; i < 16; i++) {
                int idx = tid + i * 256;
                CP_ASYNC16(dst + idx * 16, src + idx * 16);
            }
            CP_COMMIT();
            CP_WAIT1();
        } else {
            CP_WAIT0();
        }
        __syncthreads();

        const uint32_t bbase = sb + OFF_B + p * 65536;

        #pragma unroll
        for (int kstep = 0; kstep < 16; kstep++) {
            const int kc = kstep >> 2, j8 = kstep & 3;
            const uint32_t xa = (uint32_t)(((2 * j8 + cselA) ^ rsel) << 4);
            const uint32_t xb = (uint32_t)(((2 * j8 + cselB) ^ rsel) << 4);
            const uint32_t aph = sb + OFF_A_HI + kc * 16384 + rowOffA + xa;
            const uint32_t bp  = bbase + kc * 16384 + rowOffB + xb;
            uint32_t ah0[4], ah1[4], b0[4], b1[4], b2[4], b3[4];
            LDSM4(ah0, aph);
            LDSM4(ah1, aph + 2048);               // +16 rows (m)
            LDSM4(b0, bp);                         // n +0..15
            LDSM4(b1, bp + 2048);                  // n +16..31
            LDSM4(b2, bp + 4096);                  // n +32..47
            LDSM4(b3, bp + 6144);                  // n +48..63
            MMA_TF32(acc[0][0], ah0, b0[0], b0[1]);
            MMA_TF32(acc[0][1], ah0, b0[2], b0[3]);
            MMA_TF32(acc[0][2], ah0, b1[0], b1[1]);
            MMA_TF32(acc[0][3], ah0, b1[2], b1[3]);
            MMA_TF32(acc[0][4], ah0, b2[0], b2[1]);
            MMA_TF32(acc[0][5], ah0, b2[2], b2[3]);
            MMA_TF32(acc[0][6], ah0, b3[0], b3[1]);
            MMA_TF32(acc[0][7], ah0, b3[2], b3[3]);
            MMA_TF32(acc[1][0], ah1, b0[0], b0[1]);
            MMA_TF32(acc[1][1], ah1, b0[2], b0[3]);
            MMA_TF32(acc[1][2], ah1, b1[0], b1[1]);
            MMA_TF32(acc[1][3], ah1, b1[2], b1[3]);
            MMA_TF32(acc[1][4], ah1, b2[0], b2[1]);
            MMA_TF32(acc[1][5], ah1, b2[2], b2[3]);
            MMA_TF32(acc[1][6], ah1, b3[0], b3[1]);
            MMA_TF32(acc[1][7], ah1, b3[2], b3[3]);
        }

        // epilogue: rounding-emulated dist, best-2 tracking (codes ascend)
        #pragma unroll
        for (int nt = 0; nt < 8; nt++) {
            const int cbse = s * 128 + warpN * 64 + nt * 8 + 2 * tig;
            const float cn0 = cns[cbse];
            const float cn1 = cns[cbse + 1];
            #pragma unroll
            for (int mt = 0; mt < 2; mt++) {
                #pragma unroll
                for (int h = 0; h < 2; h++) {
                    const float xn = xnr[mt * 2 + h];
                    float t0 = __fadd_rn(xn, cn0);
                    float d0 = __fmaf_rn(acc[mt][nt][h * 2 + 0], -2.0f, t0);
                    d0 = fmaxf(d0, 0.0f);
                    if (d0 < bv1[mt][h]) {
                        bv2[mt][h] = bv1[mt][h]; bi2[mt][h] = bi1[mt][h];
                        bv1[mt][h] = d0;         bi1[mt][h] = cbse;
                    } else if (d0 < bv2[mt][h]) {
                        bv2[mt][h] = d0;         bi2[mt][h] = cbse;
                    }
                    float t1 = __fadd_rn(xn, cn1);
                    float d1 = __fmaf_rn(acc[mt][nt][h * 2 + 1], -2.0f, t1);
                    d1 = fmaxf(d1, 0.0f);
                    if (d1 < bv1[mt][h]) {
                        bv2[mt][h] = bv1[mt][h]; bi2[mt][h] = bi1[mt][h];
                        bv1[mt][h] = d1;         bi1[mt][h] = cbse + 1;
                    } else if (d1 < bv2[mt][h]) {
                        bv2[mt][h] = d1;         bi2[mt][h] = cbse + 1;
                    }
                }
            }
        }
        #pragma unroll
        for (int mt = 0; mt < 2; mt++)
            #pragma unroll
            for (int nt = 0; nt < 8; nt++)
                #pragma unroll
                for (int q = 0; q < 4; q++) acc[mt][nt][q] = 0.f;
        __syncthreads();
    }

    // ---- dump 16 candidates per row ----
    {
        const int slot = warpN * 4 + tig;
        #pragma unroll
        for (int mt = 0; mt < 2; mt++)
            #pragma unroll
            for (int h = 0; h < 2; h++) {
                int r = m0 + mt * 16 + h * 8 + g;
                int row = row0 + r;
                if (row < nrows) {
                    size_t b = (size_t)row * 16 + slot * 2;
                    g_cand_v[b]     = bv1[mt][h];
                    g_cand_i[b]     = bi1[mt][h];
                    g_cand_v[b + 1] = bv2[mt][h];
                    g_cand_i[b + 1] = bi2[mt][h];
                }
            }
    }
}

// ---------------------------------------------------------------------------
// Kernel 3: fused rescore + gather. One warp per row.
// ---------------------------------------------------------------------------
__global__ __launch_bounds__(256) void rescore_gather_kernel(
    const float* __restrict__ x, const float* __restrict__ cb,
    float* __restrict__ z, int nrows)
{
    __shared__ float xs[8][DDIM];
    __shared__ float ssum[8];
    const int warp = threadIdx.x >> 5;
    const int lane = threadIdx.x & 31;
    const int row  = blockIdx.x * 8 + warp;
    const bool rok = (row < nrows);

    // candidate scan
    float v = 3.4e38f;
    int   ci = 0;
    if (rok && lane < 16) {
        v  = g_cand_v[(size_t)row * 16 + lane];
        ci = g_cand_i[(size_t)row * 16 + lane];
    }
    float vmin = v;
    #pragma unroll
    for (int o = 16; o > 0; o >>= 1)
        vmin = fminf(vmin, __shfl_xor_sync(0xffffffffu, vmin, o));

    const bool active = rok && (lane < 16) && (v <= vmin + MARGIN);
    const unsigned int bal = __ballot_sync(0xffffffffu, active);

    // x row (always needed for gather)
    float4 xv = make_float4(0.f, 0.f, 0.f, 0.f);
    if (rok) xv = ((const float4*)(x + (size_t)row * DDIM))[lane];

    int ii = 0;
    if (__popc(bal) == 1) {
        int src = __ffs(bal) - 1;
        ii = __shfl_sync(0xffffffffu, ci, src);
    } else {
        // slow path: exact rescore (round-4 arithmetic, first-index tie-break)
        *(float4*)(&xs[warp][lane * 4]) = xv;
        double pn = (double)xv.x * xv.x + (double)xv.y * xv.y
                  + (double)xv.z * xv.z + (double)xv.w * xv.w;
        #pragma unroll
        for (int o = 16; o > 0; o >>= 1)
            pn += __shfl_xor_sync(0xffffffffu, pn, o);
        const float xn = (float)pn;
        __syncwarp();

        float dd = 3.4e38f;
        int   di = 0x7fffffff;
        if (active) {
            const float* cr = cb + (size_t)ci * DDIM;
            const float* xw = xs[warp];
            float acc = 0.f;
            #pragma unroll 16
            for (int d = 0; d < DDIM; d++)
                acc = __fmaf_rn(xw[d], __ldg(&cr[d]), acc);
            float t = __fadd_rn(xn, g_cnorm[ci]);
            dd = fmaxf(__fmaf_rn(acc, -2.0f, t), 0.0f);
            di = ci;
        }
        #pragma unroll
        for (int o = 16; o > 0; o >>= 1) {
            float ov = __shfl_xor_sync(0xffffffffu, dd, o);
            int   oi = __shfl_xor_sync(0xffffffffu, di, o);
            if (ov < dd || (ov == dd && oi < di)) { dd = ov; di = oi; }
        }
        ii = di;
    }

    // gather + z_st + losses
    float local = 0.f;
    if (rok) {
        const float4* cr = (const float4*)(cb + (size_t)ii * DDIM);
        float4*       zr = (float4*)(z + (size_t)row * DDIM);
        float4 cv = cr[lane];
        float dx = __fadd_rn(cv.x, -xv.x);
        float dy = __fadd_rn(cv.y, -xv.y);
        float dz = __fadd_rn(cv.z, -xv.z);
        float dw = __fadd_rn(cv.w, -xv.w);
        float4 ov;
        ov.x = __fadd_rn(xv.x, dx);
        ov.y = __fadd_rn(xv.y, dy);
        ov.z = __fadd_rn(xv.z, dz);
        ov.w = __fadd_rn(xv.w, dw);
        zr[lane] = ov;
        local = dx * dx + dy * dy + dz * dz + dw * dw;
        if (lane == 0) atomicAdd(&g_counts[ii], 1u);
    }
    #pragma unroll
    for (int o = 16; o > 0; o >>= 1) local += __shfl_down_sync(0xffffffffu, local, o);
    if (lane == 0) ssum[warp] = local;
    __syncthreads();
    if (threadIdx.x == 0) {
        float s = 0.f;
        #pragma unroll
        for (int w = 0; w < 8; w++) s += ssum[w];
        atomicAdd(&g_sumsq, s);
    }
}

// ---------------------------------------------------------------------------
// Kernel 4: losses + perplexity scalars.
// ---------------------------------------------------------------------------
__global__ __launch_bounds__(256) void finalize_kernel(
    float* __restrict__ out, long long zoff, int nrows, int K)
{
    __shared__ float sh[256];
    int t = threadIdx.x;
    float term = 0.f;
    float inv_n = 1.f / (float)nrows;
    for (int i = t; i < K; i += 256) {
        float p = (float)g_counts[i] * inv_n;
        term += p * logf(p + 1e-10f);
    }
    sh[t] = term;
    __syncthreads();
    for (int s = 128; s > 0; s >>= 1) {
        if (t < s) sh[t] += sh[t + s];
        __syncthreads();
    }
    if (t == 0) {
        float q = g_sumsq / ((float)nrows * (float)DDIM);
        out[zoff + 0] = q;
        out[zoff + 1] = q;
        out[zoff + 2] = expf(-sh[0]);
    }
}

// ---------------------------------------------------------------------------
extern "C" void kernel_launch(void* const* d_in, const int* in_sizes, int n_in,
                              void* d_out, int out_size)
{
    const float* x  = (const float*)d_in[0];
    const float* cb = (const float*)d_in[1];
    float* out = (float*)d_out;

    int nx    = in_sizes[0];
    int nrows = nx / DDIM;
    int K     = in_sizes[1] / DDIM;

    cudaFuncSetAttribute(argmin_mma, cudaFuncAttributeMaxDynamicSharedMemorySize, SMEM_BYTES);

    prep_kernel<<<K, 128>>>(cb, K);
    argmin_mma<<<(nrows + 127) / 128, 256, SMEM_BYTES>>>(x, nrows, K);
    rescore_gather_kernel<<<(nrows + 7) / 8, 256>>>(x, cb, out, nrows);
    finalize_kernel<<<1, 256>>>(out, (long long)nx, nrows, K);
}

// round 12
// speedup vs baseline: 2.8382x; 1.0725x over previous
#include <cuda_runtime.h>
#include <cstdint>
#include <math.h>

#define DDIM    128
#define MAXROWS (1 << 17)
#define MAXK    2048
#define MARGIN  2e-4f

// ---------------- scratch (static device memory only) ----------------
__device__ int          g_idx[MAXROWS];
__device__ float        g_cnorm[MAXK];
__device__ unsigned int g_counts[MAXK];
__device__ float        g_sumsq;
// codebook tf32-hi, pre-swizzled smem image (128-code chunks of 64KB:
// 4 k-panels x [128 rows x 128B], rows XOR-swizzled)
__device__ float        g_cbhi[MAXK * DDIM];
// 32 argmin candidates per row (16 slots x best-2) from the approx pass
__device__ float        g_cand_v[MAXROWS * 32];
__device__ int          g_cand_i[MAXROWS * 32];

// ---------------- smem layout ----------------
#define OFF_A_HI  0        // 65536 : 4 panels x (128 rows x 128B)
#define OFF_B     65536    // 131072: 2 bufs x 65536 (one 128-code chunk)
#define OFF_CNORM 196608   // 4096
#define OFF_XN    200704   // 512
#define OFF_XNP   201216   // 4096 : double[512]
#define SMEM_BYTES 205312

// ---------------- ptx helpers (family-portable only) ----------------
__device__ __forceinline__ uint32_t smem_u32(const void* p) {
    uint32_t a;
    asm("{ .reg .u64 t; cvta.to.shared.u64 t, %1; cvt.u32.u64 %0, t; }" : "=r"(a) : "l"(p));
    return a;
}
__device__ __forceinline__ uint32_t f2tf32(float v) {
    uint32_t r;
    asm("cvt.rna.tf32.f32 %0, %1;" : "=r"(r) : "f"(v));
    return r;
}
#define LDSM4(R, addr) \
    asm volatile("ldmatrix.sync.aligned.m8n8.x4.shared.b16 {%0,%1,%2,%3}, [%4];" \
        : "=r"((R)[0]), "=r"((R)[1]), "=r"((R)[2]), "=r"((R)[3]) : "r"(addr))
#define MMA_TF32(C, A, b0, b1) \
    asm volatile("mma.sync.aligned.m16n8k8.row.col.f32.tf32.tf32.f32 " \
        "{%0,%1,%2,%3}, {%4,%5,%6,%7}, {%8,%9}, {%0,%1,%2,%3};" \
        : "+f"((C)[0]), "+f"((C)[1]), "+f"((C)[2]), "+f"((C)[3]) \
        : "r"((A)[0]), "r"((A)[1]), "r"((A)[2]), "r"((A)[3]), "r"(b0), "r"(b1))
#define CP_ASYNC16(dst, src) \
    asm volatile("cp.async.cg.shared.global [%0], [%1], 16;" :: "r"(dst), "l"(src))
#define CP_COMMIT()  asm volatile("cp.async.commit_group;" ::: "memory")
#define CP_WAIT1()   asm volatile("cp.async.wait_group 1;" ::: "memory")
#define CP_WAIT0()   asm volatile("cp.async.wait_group 0;" ::: "memory")

// ---------------------------------------------------------------------------
// Kernel 1: codebook -> tf32 hi (pre-swizzled 128-code-chunk layout), exact
// fp64 cnorm, zero accumulators. One block per code, 128 threads.
// ---------------------------------------------------------------------------
__global__ __launch_bounds__(128) void prep_kernel(const float* __restrict__ cb, int K)
{
    __shared__ double red[128];
    int k = blockIdx.x;
    int d = threadIdx.x;
    float v = cb[(size_t)k * DDIM + d];
    float hi = __uint_as_float(f2tf32(v));

    int chunk = k >> 7, cloc = k & 127;
    int kc = d >> 5, e = d & 31;
    int col16 = e >> 2, w = e & 3;
    int off = cloc * 32 + (((col16 ^ (cloc & 7)) << 2) + w);
    g_cbhi[chunk * 16384 + kc * 4096 + off] = hi;

    red[d] = (double)v * (double)v;
    __syncthreads();
    for (int s = 64; s > 0; s >>= 1) {
        if (d < s) red[d] += red[d + s];
        __syncthreads();
    }
    if (d == 0) g_cnorm[k] = (float)red[0];

    if (k == 0) {
        for (int i = d; i < K; i += 128) g_counts[i] = 0u;
        if (d == 0) g_sumsq = 0.f;
    }
}

// ---------------------------------------------------------------------------
// Kernel 2: single-pass tf32 mma.sync GEMM, 16 warps (4M x 4N), warp tile
// m32 x n32, 128-code chunks; rounding-emulated dist; emits 32 candidates
// per row (16 slots x best-2, ascending-code).
// ---------------------------------------------------------------------------
__global__ __launch_bounds__(512, 1) void argmin_mma(
    const float* __restrict__ x, int nrows, int K)
{
    extern __shared__ char smc[];
    const uint32_t sb = smem_u32(smc);

    const int tid  = threadIdx.x;
    const int warp = tid >> 5;
    const int lane = tid & 31;
    const int row0 = blockIdx.x * 128;
    const int nsteps = K >> 7;                 // 128-code chunks

    // ---- kick off first B fill (chunk 0, 64KB) ----
    {
        const char* src = (const char*)g_cbhi;
        #pragma unroll
        for (int i = 0; i < 8; i++) {
            int idx = tid + i * 512;           // 4096 float4
            CP_ASYNC16(sb + OFF_B + idx * 16, src + idx * 16);
        }
        CP_COMMIT();
    }

    // ---- stage A (tf32 hi, swizzled) + fp64 norm partials ----
    {
        int r = tid >> 2, q = tid & 3;         // 4 threads per row
        int row = row0 + r;
        const float4* xr = (const float4*)(x + (size_t)row * DDIM);
        double pn = 0.0;
        #pragma unroll
        for (int i = 0; i < 8; i++) {
            int e4 = q * 8 + i;                // float4 index 0..31
            float4 v = make_float4(0.f, 0.f, 0.f, 0.f);
            if (row < nrows) v = xr[e4];
            float4 hv;
            hv.x = __uint_as_float(f2tf32(v.x));
            hv.y = __uint_as_float(f2tf32(v.y));
            hv.z = __uint_as_float(f2tf32(v.z));
            hv.w = __uint_as_float(f2tf32(v.w));
            pn += (double)v.x * v.x + (double)v.y * v.y
                + (double)v.z * v.z + (double)v.w * v.w;
            int kc = e4 >> 3, c16 = e4 & 7;
            int boff = kc * 16384 + r * 128 + ((c16 ^ (r & 7)) << 4);
            *(float4*)(smc + OFF_A_HI + boff) = hv;
        }
        ((double*)(smc + OFF_XNP))[tid] = pn;
    }
    for (int i = tid; i < K; i += 512)
        ((float*)(smc + OFF_CNORM))[i] = g_cnorm[i];
    __syncthreads();
    if (tid < 128) {
        const double* p = (const double*)(smc + OFF_XNP);
        ((float*)(smc + OFF_XN))[tid] =
            (float)((p[4 * tid] + p[4 * tid + 1]) + (p[4 * tid + 2] + p[4 * tid + 3]));
    }
    __syncthreads();

    // ---- per-lane constants ----
    const int warpM = warp >> 2, warpN = warp & 3;   // 4M x 4N
    const int m0 = warpM * 32;
    const int g   = lane >> 2, tig = lane & 3;
    const int rsel = lane & 7;
    const int mselA = (lane >> 3) & 1, cselA = lane >> 4;
    const uint32_t rowOffA = (uint32_t)(m0 + mselA * 8 + rsel) * 128;
    const int cselB = (lane >> 3) & 1, nselB = lane >> 4;
    const uint32_t rowOffB = (uint32_t)(warpN * 32 + nselB * 8 + rsel) * 128;

    const float* xns = (const float*)(smc + OFF_XN);
    float xnr[4];
    #pragma unroll
    for (int mt = 0; mt < 2; mt++)
        #pragma unroll
        for (int h = 0; h < 2; h++)
            xnr[mt * 2 + h] = xns[m0 + mt * 16 + h * 8 + g];

    const float* cns = (const float*)(smc + OFF_CNORM);

    float acc[2][4][4];
    #pragma unroll
    for (int mt = 0; mt < 2; mt++)
        #pragma unroll
        for (int nt = 0; nt < 4; nt++)
            #pragma unroll
            for (int q = 0; q < 4; q++) acc[mt][nt][q] = 0.f;

    // best-2 per (mt,h) row-slot, ascending-code update preserves first-index
    float bv1[2][2], bv2[2][2];
    int   bi1[2][2], bi2[2][2];
    #pragma unroll
    for (int mt = 0; mt < 2; mt++)
        #pragma unroll
        for (int h = 0; h < 2; h++) {
            bv1[mt][h] = 3.4e38f; bi1[mt][h] = 0;
            bv2[mt][h] = 3.4e38f; bi2[mt][h] = 0;
        }

    for (int s = 0; s < nsteps; s++) {
        const int p = s & 1;
        if (s + 1 < nsteps) {
            const char* src = (const char*)(g_cbhi + (size_t)(s + 1) * 16384);
            uint32_t dst = sb + OFF_B + (p ^ 1) * 65536;
            #pragma unroll
            for (int i = 0; i < 8; i++) {
                int idx = tid + i * 512;
                CP_ASYNC16(dst + idx * 16, src + idx * 16);
            }
            CP_COMMIT();
            CP_WAIT1();
        } else {
            CP_WAIT0();
        }
        __syncthreads();

        const uint32_t bbase = sb + OFF_B + p * 65536;

        #pragma unroll
        for (int kstep = 0; kstep < 16; kstep++) {
            const int kc = kstep >> 2, j8 = kstep & 3;
            const uint32_t xa = (uint32_t)(((2 * j8 + cselA) ^ rsel) << 4);
            const uint32_t xb = (uint32_t)(((2 * j8 + cselB) ^ rsel) << 4);
            const uint32_t aph = sb + OFF_A_HI + kc * 16384 + rowOffA + xa;
            const uint32_t bp  = bbase + kc * 16384 + rowOffB + xb;
            uint32_t ah0[4], ah1[4], b0[4], b1[4];
            LDSM4(ah0, aph);
            LDSM4(ah1, aph + 2048);               // +16 rows (m)
            LDSM4(b0, bp);                         // n +0..15
            LDSM4(b1, bp + 2048);                  // n +16..31
            MMA_TF32(acc[0][0], ah0, b0[0], b0[1]);
            MMA_TF32(acc[0][1], ah0, b0[2], b0[3]);
            MMA_TF32(acc[0][2], ah0, b1[0], b1[1]);
            MMA_TF32(acc[0][3], ah0, b1[2], b1[3]);
            MMA_TF32(acc[1][0], ah1, b0[0], b0[1]);
            MMA_TF32(acc[1][1], ah1, b0[2], b0[3]);
            MMA_TF32(acc[1][2], ah1, b1[0], b1[1]);
            MMA_TF32(acc[1][3], ah1, b1[2], b1[3]);
        }

        // epilogue: rounding-emulated dist, best-2 tracking (codes ascend)
        #pragma unroll
        for (int nt = 0; nt < 4; nt++) {
            const int cbse = s * 128 + warpN * 32 + nt * 8 + 2 * tig;
            const float cn0 = cns[cbse];
            const float cn1 = cns[cbse + 1];
            #pragma unroll
            for (int mt = 0; mt < 2; mt++) {
                #pragma unroll
                for (int h = 0; h < 2; h++) {
                    const float xn = xnr[mt * 2 + h];
                    float t0 = __fadd_rn(xn, cn0);
                    float d0 = __fmaf_rn(acc[mt][nt][h * 2 + 0], -2.0f, t0);
                    d0 = fmaxf(d0, 0.0f);
                    if (d0 < bv1[mt][h]) {
                        bv2[mt][h] = bv1[mt][h]; bi2[mt][h] = bi1[mt][h];
                        bv1[mt][h] = d0;         bi1[mt][h] = cbse;
                    } else if (d0 < bv2[mt][h]) {
                        bv2[mt][h] = d0;         bi2[mt][h] = cbse;
                    }
                    float t1 = __fadd_rn(xn, cn1);
                    float d1 = __fmaf_rn(acc[mt][nt][h * 2 + 1], -2.0f, t1);
                    d1 = fmaxf(d1, 0.0f);
                    if (d1 < bv1[mt][h]) {
                        bv2[mt][h] = bv1[mt][h]; bi2[mt][h] = bi1[mt][h];
                        bv1[mt][h] = d1;         bi1[mt][h] = cbse + 1;
                    } else if (d1 < bv2[mt][h]) {
                        bv2[mt][h] = d1;         bi2[mt][h] = cbse + 1;
                    }
                }
            }
        }
        #pragma unroll
        for (int mt = 0; mt < 2; mt++)
            #pragma unroll
            for (int nt = 0; nt < 4; nt++)
                #pragma unroll
                for (int q = 0; q < 4; q++) acc[mt][nt][q] = 0.f;
        __syncthreads();
    }

    // ---- dump 32 candidates per row (16 slots x best-2) ----
    {
        const int slot = warpN * 4 + tig;      // 0..15
        #pragma unroll
        for (int mt = 0; mt < 2; mt++)
            #pragma unroll
            for (int h = 0; h < 2; h++) {
                int r = m0 + mt * 16 + h * 8 + g;
                int row = row0 + r;
                if (row < nrows) {
                    size_t b = (size_t)row * 32 + slot * 2;
                    g_cand_v[b]     = bv1[mt][h];
                    g_cand_i[b]     = bi1[mt][h];
                    g_cand_v[b + 1] = bv2[mt][h];
                    g_cand_i[b + 1] = bi2[mt][h];
                }
            }
    }
}

// ---------------------------------------------------------------------------
// Kernel 3: fused rescore + gather. One warp per row; 32 candidates/row.
// ---------------------------------------------------------------------------
__global__ __launch_bounds__(256) void rescore_gather_kernel(
    const float* __restrict__ x, const float* __restrict__ cb,
    float* __restrict__ z, int nrows)
{
    __shared__ float xs[8][DDIM];
    __shared__ float ssum[8];
    const int warp = threadIdx.x >> 5;
    const int lane = threadIdx.x & 31;
    const int row  = blockIdx.x * 8 + warp;
    const bool rok = (row < nrows);

    // candidate scan: one candidate per lane
    float v = 3.4e38f;
    int   ci = 0;
    if (rok) {
        v  = g_cand_v[(size_t)row * 32 + lane];
        ci = g_cand_i[(size_t)row * 32 + lane];
    }
    float vmin = v;
    #pragma unroll
    for (int o = 16; o > 0; o >>= 1)
        vmin = fminf(vmin, __shfl_xor_sync(0xffffffffu, vmin, o));

    const bool active = rok && (v <= vmin + MARGIN);
    const unsigned int bal = __ballot_sync(0xffffffffu, active);

    // x row (always needed for gather)
    float4 xv = make_float4(0.f, 0.f, 0.f, 0.f);
    if (rok) xv = ((const float4*)(x + (size_t)row * DDIM))[lane];

    int ii = 0;
    if (__popc(bal) == 1) {
        int src = __ffs(bal) - 1;
        ii = __shfl_sync(0xffffffffu, ci, src);
    } else {
        // slow path: exact rescore (round-4 arithmetic, first-index tie-break)
        *(float4*)(&xs[warp][lane * 4]) = xv;
        double pn = (double)xv.x * xv.x + (double)xv.y * xv.y
                  + (double)xv.z * xv.z + (double)xv.w * xv.w;
        #pragma unroll
        for (int o = 16; o > 0; o >>= 1)
            pn += __shfl_xor_sync(0xffffffffu, pn, o);
        const float xn = (float)pn;
        __syncwarp();

        float dd = 3.4e38f;
        int   di = 0x7fffffff;
        if (active) {
            const float* cr = cb + (size_t)ci * DDIM;
            const float* xw = xs[warp];
            float acc = 0.f;
            #pragma unroll 16
            for (int d = 0; d < DDIM; d++)
                acc = __fmaf_rn(xw[d], __ldg(&cr[d]), acc);
            float t = __fadd_rn(xn, g_cnorm[ci]);
            dd = fmaxf(__fmaf_rn(acc, -2.0f, t), 0.0f);
            di = ci;
        }
        #pragma unroll
        for (int o = 16; o > 0; o >>= 1) {
            float ov = __shfl_xor_sync(0xffffffffu, dd, o);
            int   oi = __shfl_xor_sync(0xffffffffu, di, o);
            if (ov < dd || (ov == dd && oi < di)) { dd = ov; di = oi; }
        }
        ii = di;
    }

    // gather + z_st + losses
    float local = 0.f;
    if (rok) {
        const float4* cr = (const float4*)(cb + (size_t)ii * DDIM);
        float4*       zr = (float4*)(z + (size_t)row * DDIM);
        float4 cv = cr[lane];
        float dx = __fadd_rn(cv.x, -xv.x);
        float dy = __fadd_rn(cv.y, -xv.y);
        float dz = __fadd_rn(cv.z, -xv.z);
        float dw = __fadd_rn(cv.w, -xv.w);
        float4 ov;
        ov.x = __fadd_rn(xv.x, dx);
        ov.y = __fadd_rn(xv.y, dy);
        ov.z = __fadd_rn(xv.z, dz);
        ov.w = __fadd_rn(xv.w, dw);
        zr[lane] = ov;
        local = dx * dx + dy * dy + dz * dz + dw * dw;
        if (lane == 0) atomicAdd(&g_counts[ii], 1u);
    }
    #pragma unroll
    for (int o = 16; o > 0; o >>= 1) local += __shfl_down_sync(0xffffffffu, local, o);
    if (lane == 0) ssum[warp] = local;
    __syncthreads();
    if (threadIdx.x == 0) {
        float s = 0.f;
        #pragma unroll
        for (int w = 0; w < 8; w++) s += ssum[w];
        atomicAdd(&g_sumsq, s);
    }
}

// ---------------------------------------------------------------------------
// Kernel 4: losses + perplexity scalars.
// ---------------------------------------------------------------------------
__global__ __launch_bounds__(256) void finalize_kernel(
    float* __restrict__ out, long long zoff, int nrows, int K)
{
    __shared__ float sh[256];
    int t = threadIdx.x;
    float term = 0.f;
    float inv_n = 1.f / (float)nrows;
    for (int i = t; i < K; i += 256) {
        float p = (float)g_counts[i] * inv_n;
        term += p * logf(p + 1e-10f);
    }
    sh[t] = term;
    __syncthreads();
    for (int s = 128; s > 0; s >>= 1) {
        if (t < s) sh[t] += sh[t + s];
        __syncthreads();
    }
    if (t == 0) {
        float q = g_sumsq / ((float)nrows * (float)DDIM);
        out[zoff + 0] = q;
        out[zoff + 1] = q;
        out[zoff + 2] = expf(-sh[0]);
    }
}

// ---------------------------------------------------------------------------
extern "C" void kernel_launch(void* const* d_in, const int* in_sizes, int n_in,
                              void* d_out, int out_size)
{
    const float* x  = (const float*)d_in[0];
    const float* cb = (const float*)d_in[1];
    float* out = (float*)d_out;

    int nx    = in_sizes[0];
    int nrows = nx / DDIM;
    int K     = in_sizes[1] / DDIM;

    cudaFuncSetAttribute(argmin_mma, cudaFuncAttributeMaxDynamicSharedMemorySize, SMEM_BYTES);

    prep_kernel<<<K, 128>>>(cb, K);
    argmin_mma<<<(nrows + 127) / 128, 512, SMEM_BYTES>>>(x, nrows, K);
    rescore_gather_kernel<<<(nrows + 7) / 8, 256>>>(x, cb, out, nrows);
    finalize_kernel<<<1, 256>>>(out, (long long)nx, nrows, K);
}

// round 13
// speedup vs baseline: 3.3933x; 1.1956x over previous
#include <cuda_runtime.h>
#include <cuda_bf16.h>
#include <cstdint>
#include <math.h>

#define DDIM    128
#define MAXROWS (1 << 17)
#define MAXK    2048
#define MARGIN  1e-3f

// ---------------- scratch (static device memory only) ----------------
__device__ int            g_idx[MAXROWS];
__device__ float          g_cnorm[MAXK];
__device__ unsigned int   g_counts[MAXK];
__device__ float          g_sumsq;
// codebook as bf16, pre-swizzled smem image: per 128-code chunk (32KB):
// 2 k-panels x [128 code-rows x 128B], rows XOR-swizzled
__device__ unsigned short g_cbh[MAXK * DDIM];
// 32 argmin candidates per row (16 slots x best-2) from the approx pass
__device__ float          g_cand_v[MAXROWS * 32];
__device__ int            g_cand_i[MAXROWS * 32];

// ---------------- smem layout ----------------
#define OFF_A     0        // 32768 : 2 panels x (128 rows x 128B) bf16
#define OFF_B     32768    // 65536 : 2 bufs x 32768 (one 128-code chunk)
#define OFF_CNORM 98304    // 4096
#define OFF_XN    102400   // 512
#define OFF_XNP   102912   // 4096 : double[512]
#define SMEM_BYTES 107008

// ---------------- ptx helpers (family-portable only) ----------------
__device__ __forceinline__ uint32_t smem_u32(const void* p) {
    uint32_t a;
    asm("{ .reg .u64 t; cvta.to.shared.u64 t, %1; cvt.u32.u64 %0, t; }" : "=r"(a) : "l"(p));
    return a;
}
#define LDSM4(R, addr) \
    asm volatile("ldmatrix.sync.aligned.m8n8.x4.shared.b16 {%0,%1,%2,%3}, [%4];" \
        : "=r"((R)[0]), "=r"((R)[1]), "=r"((R)[2]), "=r"((R)[3]) : "r"(addr))
#define MMA_BF16(C, A, b0, b1) \
    asm volatile("mma.sync.aligned.m16n8k16.row.col.f32.bf16.bf16.f32 " \
        "{%0,%1,%2,%3}, {%4,%5,%6,%7}, {%8,%9}, {%0,%1,%2,%3};" \
        : "+f"((C)[0]), "+f"((C)[1]), "+f"((C)[2]), "+f"((C)[3]) \
        : "r"((A)[0]), "r"((A)[1]), "r"((A)[2]), "r"((A)[3]), "r"(b0), "r"(b1))
#define CP_ASYNC16(dst, src) \
    asm volatile("cp.async.cg.shared.global [%0], [%1], 16;" :: "r"(dst), "l"(src))
#define CP_COMMIT()  asm volatile("cp.async.commit_group;" ::: "memory")
#define CP_WAIT1()   asm volatile("cp.async.wait_group 1;" ::: "memory")
#define CP_WAIT0()   asm volatile("cp.async.wait_group 0;" ::: "memory")

__device__ __forceinline__ unsigned short f2bf(float v) {
    return __bfloat16_as_ushort(__float2bfloat16(v));
}

// ---------------------------------------------------------------------------
// Kernel 1: codebook -> bf16 (pre-swizzled 128-code-chunk layout), exact
// fp64 cnorm, zero accumulators. One block per code, 128 threads (1/dim).
// ---------------------------------------------------------------------------
__global__ __launch_bounds__(128) void prep_kernel(const float* __restrict__ cb, int K)
{
    __shared__ double red[128];
    int k = blockIdx.x;
    int d = threadIdx.x;
    float v = cb[(size_t)k * DDIM + d];

    int chunk = k >> 7, cloc = k & 127;
    int kc = d >> 6, e = d & 63;          // panel, elem-in-panel (64 bf16/row)
    int u = e >> 3, w = e & 7;            // 16B unit, elem-in-unit
    // ushort index: chunk*16384 + panel*8192 + row*64 + swizzled unit*8 + w
    int idx = chunk * 16384 + kc * 8192 + cloc * 64 + ((u ^ (cloc & 7)) << 3) + w;
    g_cbh[idx] = f2bf(v);

    red[d] = (double)v * (double)v;
    __syncthreads();
    for (int s = 64; s > 0; s >>= 1) {
        if (d < s) red[d] += red[d + s];
        __syncthreads();
    }
    if (d == 0) g_cnorm[k] = (float)red[0];

    if (k == 0) {
        for (int i = d; i < K; i += 128) g_counts[i] = 0u;
        if (d == 0) g_sumsq = 0.f;
    }
}

// ---------------------------------------------------------------------------
// Kernel 2: single-pass bf16 mma.sync m16n8k16 GEMM, 16 warps (4M x 4N),
// warp tile m32 x n32, 128-code chunks; rounding-emulated dist; emits 32
// candidates per row (16 slots x best-2, ascending-code).
// ---------------------------------------------------------------------------
__global__ __launch_bounds__(512, 1) void argmin_mma(
    const float* __restrict__ x, int nrows, int K)
{
    extern __shared__ char smc[];
    const uint32_t sb = smem_u32(smc);

    const int tid  = threadIdx.x;
    const int warp = tid >> 5;
    const int lane = tid & 31;
    const int row0 = blockIdx.x * 128;
    const int nsteps = K >> 7;                 // 128-code chunks

    // ---- kick off first B fill (chunk 0, 32KB) ----
    {
        const char* src = (const char*)g_cbh;
        #pragma unroll
        for (int i = 0; i < 4; i++) {
            int idx = tid + i * 512;           // 2048 float4
            CP_ASYNC16(sb + OFF_B + idx * 16, src + idx * 16);
        }
        CP_COMMIT();
    }

    // ---- stage A (bf16, swizzled panels) + fp64 norm partials ----
    {
        int r = tid >> 2, q = tid & 3;         // 4 threads per row, 32 dims each
        int row = row0 + r;
        const float4* xr = (const float4*)(x + (size_t)row * DDIM);
        int kc = q >> 1, hh = q & 1;           // panel, half-of-panel
        double pn = 0.0;
        #pragma unroll
        for (int i = 0; i < 4; i++) {
            int u = hh * 4 + i;                // unit within panel (8 bf16)
            int e4 = kc * 16 + u * 2;          // float4 index of first 4 dims
            float4 va = make_float4(0.f, 0.f, 0.f, 0.f);
            float4 vb = make_float4(0.f, 0.f, 0.f, 0.f);
            if (row < nrows) { va = xr[e4]; vb = xr[e4 + 1]; }
            pn += (double)va.x * va.x + (double)va.y * va.y
                + (double)va.z * va.z + (double)va.w * va.w
                + (double)vb.x * vb.x + (double)vb.y * vb.y
                + (double)vb.z * vb.z + (double)vb.w * vb.w;
            uint32_t p0 = (uint32_t)f2bf(va.x) | ((uint32_t)f2bf(va.y) << 16);
            uint32_t p1 = (uint32_t)f2bf(va.z) | ((uint32_t)f2bf(va.w) << 16);
            uint32_t p2 = (uint32_t)f2bf(vb.x) | ((uint32_t)f2bf(vb.y) << 16);
            uint32_t p3 = (uint32_t)f2bf(vb.z) | ((uint32_t)f2bf(vb.w) << 16);
            uint4 pk = make_uint4(p0, p1, p2, p3);
            int boff = kc * 16384 + r * 128 + ((u ^ (r & 7)) << 4);
            *(uint4*)(smc + OFF_A + boff) = pk;
        }
        ((double*)(smc + OFF_XNP))[tid] = pn;
    }
    for (int i = tid; i < K; i += 512)
        ((float*)(smc + OFF_CNORM))[i] = g_cnorm[i];
    __syncthreads();
    if (tid < 128) {
        const double* p = (const double*)(smc + OFF_XNP);
        ((float*)(smc + OFF_XN))[tid] =
            (float)((p[4 * tid] + p[4 * tid + 1]) + (p[4 * tid + 2] + p[4 * tid + 3]));
    }
    __syncthreads();

    // ---- per-lane constants ----
    const int warpM = warp >> 2, warpN = warp & 3;   // 4M x 4N
    const int m0 = warpM * 32;
    const int g   = lane >> 2, tig = lane & 3;
    const int rsel = lane & 7;
    const int mselA = (lane >> 3) & 1, kselA = lane >> 4;       // A groups
    const uint32_t rowOffA = (uint32_t)(m0 + mselA * 8 + rsel) * 128;
    const int kselB = (lane >> 3) & 1, nselB = lane >> 4;       // B groups
    const uint32_t rowOffB = (uint32_t)(warpN * 32 + nselB * 8 + rsel) * 128;

    const float* xns = (const float*)(smc + OFF_XN);
    float xnr[4];
    #pragma unroll
    for (int mt = 0; mt < 2; mt++)
        #pragma unroll
        for (int h = 0; h < 2; h++)
            xnr[mt * 2 + h] = xns[m0 + mt * 16 + h * 8 + g];

    const float* cns = (const float*)(smc + OFF_CNORM);

    float acc[2][4][4];
    #pragma unroll
    for (int mt = 0; mt < 2; mt++)
        #pragma unroll
        for (int nt = 0; nt < 4; nt++)
            #pragma unroll
            for (int q = 0; q < 4; q++) acc[mt][nt][q] = 0.f;

    // best-2 per (mt,h) row-slot, ascending-code update preserves first-index
    float bv1[2][2], bv2[2][2];
    int   bi1[2][2], bi2[2][2];
    #pragma unroll
    for (int mt = 0; mt < 2; mt++)
        #pragma unroll
        for (int h = 0; h < 2; h++) {
            bv1[mt][h] = 3.4e38f; bi1[mt][h] = 0;
            bv2[mt][h] = 3.4e38f; bi2[mt][h] = 0;
        }

    for (int s = 0; s < nsteps; s++) {
        const int p = s & 1;
        if (s + 1 < nsteps) {
            const char* src = (const char*)(g_cbh + (size_t)(s + 1) * 16384);
            uint32_t dst = sb + OFF_B + (p ^ 1) * 32768;
            #pragma unroll
            for (int i = 0; i < 4; i++) {
                int idx = tid + i * 512;
                CP_ASYNC16(dst + idx * 16, src + idx * 16);
            }
            CP_COMMIT();
            CP_WAIT1();
        } else {
            CP_WAIT0();
        }
        __syncthreads();

        const uint32_t bbase = sb + OFF_B + p * 32768;

        #pragma unroll
        for (int kstep = 0; kstep < 8; kstep++) {
            const int kc = kstep >> 2, j = kstep & 3;            // panel, k16-in-panel
            const uint32_t xa = (uint32_t)(((2 * j + kselA) ^ rsel) << 4);
            const uint32_t xb = (uint32_t)(((2 * j + kselB) ^ rsel) << 4);
            const uint32_t aph = sb + OFF_A + kc * 16384 + rowOffA + xa;
            const uint32_t bp  = bbase + kc * 16384 + rowOffB + xb;
            uint32_t a0[4], a1[4], b0[4], b1[4];
            LDSM4(a0, aph);                        // m 0..15 (of warp tile)
            LDSM4(a1, aph + 2048);                 // m 16..31
            LDSM4(b0, bp);                         // n 0..15 (b-pairs for 2 n8 tiles)
            LDSM4(b1, bp + 2048);                  // n 16..31
            MMA_BF16(acc[0][0], a0, b0[0], b0[1]);
            MMA_BF16(acc[0][1], a0, b0[2], b0[3]);
            MMA_BF16(acc[0][2], a0, b1[0], b1[1]);
            MMA_BF16(acc[0][3], a0, b1[2], b1[3]);
            MMA_BF16(acc[1][0], a1, b0[0], b0[1]);
            MMA_BF16(acc[1][1], a1, b0[2], b0[3]);
            MMA_BF16(acc[1][2], a1, b1[0], b1[1]);
            MMA_BF16(acc[1][3], a1, b1[2], b1[3]);
        }

        // epilogue: rounding-emulated dist, best-2 tracking (codes ascend)
        #pragma unroll
        for (int nt = 0; nt < 4; nt++) {
            const int cbse = s * 128 + warpN * 32 + nt * 8 + 2 * tig;
            const float cn0 = cns[cbse];
            const float cn1 = cns[cbse + 1];
            #pragma unroll
            for (int mt = 0; mt < 2; mt++) {
                #pragma unroll
                for (int h = 0; h < 2; h++) {
                    const float xn = xnr[mt * 2 + h];
                    float t0 = __fadd_rn(xn, cn0);
                    float d0 = __fmaf_rn(acc[mt][nt][h * 2 + 0], -2.0f, t0);
                    d0 = fmaxf(d0, 0.0f);
                    if (d0 < bv1[mt][h]) {
                        bv2[mt][h] = bv1[mt][h]; bi2[mt][h] = bi1[mt][h];
                        bv1[mt][h] = d0;         bi1[mt][h] = cbse;
                    } else if (d0 < bv2[mt][h]) {
                        bv2[mt][h] = d0;         bi2[mt][h] = cbse;
                    }
                    float t1 = __fadd_rn(xn, cn1);
                    float d1 = __fmaf_rn(acc[mt][nt][h * 2 + 1], -2.0f, t1);
                    d1 = fmaxf(d1, 0.0f);
                    if (d1 < bv1[mt][h]) {
                        bv2[mt][h] = bv1[mt][h]; bi2[mt][h] = bi1[mt][h];
                        bv1[mt][h] = d1;         bi1[mt][h] = cbse + 1;
                    } else if (d1 < bv2[mt][h]) {
                        bv2[mt][h] = d1;         bi2[mt][h] = cbse + 1;
                    }
                }
            }
        }
        #pragma unroll
        for (int mt = 0; mt < 2; mt++)
            #pragma unroll
            for (int nt = 0; nt < 4; nt++)
                #pragma unroll
                for (int q = 0; q < 4; q++) acc[mt][nt][q] = 0.f;
        __syncthreads();
    }

    // ---- dump 32 candidates per row (16 slots x best-2) ----
    {
        const int slot = warpN * 4 + tig;      // 0..15
        #pragma unroll
        for (int mt = 0; mt < 2; mt++)
            #pragma unroll
            for (int h = 0; h < 2; h++) {
                int r = m0 + mt * 16 + h * 8 + g;
                int row = row0 + r;
                if (row < nrows) {
                    size_t b = (size_t)row * 32 + slot * 2;
                    g_cand_v[b]     = bv1[mt][h];
                    g_cand_i[b]     = bi1[mt][h];
                    g_cand_v[b + 1] = bv2[mt][h];
                    g_cand_i[b + 1] = bi2[mt][h];
                }
            }
    }
}

// ---------------------------------------------------------------------------
// Kernel 3: fused rescore + gather. One warp per row; 32 candidates/row.
// Unique near-min -> direct; else exact round-4 FMA-chain rescore with
// first-index tie-break (proven zero-flip arithmetic).
// ---------------------------------------------------------------------------
__global__ __launch_bounds__(256) void rescore_gather_kernel(
    const float* __restrict__ x, const float* __restrict__ cb,
    float* __restrict__ z, int nrows)
{
    __shared__ float xs[8][DDIM];
    __shared__ float ssum[8];
    const int warp = threadIdx.x >> 5;
    const int lane = threadIdx.x & 31;
    const int row  = blockIdx.x * 8 + warp;
    const bool rok = (row < nrows);

    // candidate scan: one candidate per lane
    float v = 3.4e38f;
    int   ci = 0;
    if (rok) {
        v  = g_cand_v[(size_t)row * 32 + lane];
        ci = g_cand_i[(size_t)row * 32 + lane];
    }
    float vmin = v;
    #pragma unroll
    for (int o = 16; o > 0; o >>= 1)
        vmin = fminf(vmin, __shfl_xor_sync(0xffffffffu, vmin, o));

    const bool active = rok && (v <= vmin + MARGIN);
    const unsigned int bal = __ballot_sync(0xffffffffu, active);

    // x row (always needed for gather)
    float4 xv = make_float4(0.f, 0.f, 0.f, 0.f);
    if (rok) xv = ((const float4*)(x + (size_t)row * DDIM))[lane];

    int ii = 0;
    if (__popc(bal) == 1) {
        int src = __ffs(bal) - 1;
        ii = __shfl_sync(0xffffffffu, ci, src);
    } else {
        // slow path: exact rescore (round-4 arithmetic, first-index tie-break)
        *(float4*)(&xs[warp][lane * 4]) = xv;
        double pn = (double)xv.x * xv.x + (double)xv.y * xv.y
                  + (double)xv.z * xv.z + (double)xv.w * xv.w;
        #pragma unroll
        for (int o = 16; o > 0; o >>= 1)
            pn += __shfl_xor_sync(0xffffffffu, pn, o);
        const float xn = (float)pn;
        __syncwarp();

        float dd = 3.4e38f;
        int   di = 0x7fffffff;
        if (active) {
            const float* cr = cb + (size_t)ci * DDIM;
            const float* xw = xs[warp];
            float acc = 0.f;
            #pragma unroll 16
            for (int d = 0; d < DDIM; d++)
                acc = __fmaf_rn(xw[d], __ldg(&cr[d]), acc);
            float t = __fadd_rn(xn, g_cnorm[ci]);
            dd = fmaxf(__fmaf_rn(acc, -2.0f, t), 0.0f);
            di = ci;
        }
        #pragma unroll
        for (int o = 16; o > 0; o >>= 1) {
            float ov = __shfl_xor_sync(0xffffffffu, dd, o);
            int   oi = __shfl_xor_sync(0xffffffffu, di, o);
            if (ov < dd || (ov == dd && oi < di)) { dd = ov; di = oi; }
        }
        ii = di;
    }

    // gather + z_st + losses
    float local = 0.f;
    if (rok) {
        const float4* cr = (const float4*)(cb + (size_t)ii * DDIM);
        float4*       zr = (float4*)(z + (size_t)row * DDIM);
        float4 cv = cr[lane];
        float dx = __fadd_rn(cv.x, -xv.x);
        float dy = __fadd_rn(cv.y, -xv.y);
        float dz = __fadd_rn(cv.z, -xv.z);
        float dw = __fadd_rn(cv.w, -xv.w);
        float4 ov;
        ov.x = __fadd_rn(xv.x, dx);
        ov.y = __fadd_rn(xv.y, dy);
        ov.z = __fadd_rn(xv.z, dz);
        ov.w = __fadd_rn(xv.w, dw);
        zr[lane] = ov;
        local = dx * dx + dy * dy + dz * dz + dw * dw;
        if (lane == 0) atomicAdd(&g_counts[ii], 1u);
    }
    #pragma unroll
    for (int o = 16; o > 0; o >>= 1) local += __shfl_down_sync(0xffffffffu, local, o);
    if (lane == 0) ssum[warp] = local;
    __syncthreads();
    if (threadIdx.x == 0) {
        float s = 0.f;
        #pragma unroll
        for (int w = 0; w < 8; w++) s += ssum[w];
        atomicAdd(&g_sumsq, s);
    }
}

// ---------------------------------------------------------------------------
// Kernel 4: losses + perplexity scalars.
// ---------------------------------------------------------------------------
__global__ __launch_bounds__(256) void finalize_kernel(
    float* __restrict__ out, long long zoff, int nrows, int K)
{
    __shared__ float sh[256];
    int t = threadIdx.x;
    float term = 0.f;
    float inv_n = 1.f / (float)nrows;
    for (int i = t; i < K; i += 256) {
        float p = (float)g_counts[i] * inv_n;
        term += p * logf(p + 1e-10f);
    }
    sh[t] = term;
    __syncthreads();
    for (int s = 128; s > 0; s >>= 1) {
        if (t < s) sh[t] += sh[t + s];
        __syncthreads();
    }
    if (t == 0) {
        float q = g_sumsq / ((float)nrows * (float)DDIM);
        out[zoff + 0] = q;
        out[zoff + 1] = q;
        out[zoff + 2] = expf(-sh[0]);
    }
}

// ---------------------------------------------------------------------------
extern "C" void kernel_launch(void* const* d_in, const int* in_sizes, int n_in,
                              void* d_out, int out_size)
{
    const float* x  = (const float*)d_in[0];
    const float* cb = (const float*)d_in[1];
    float* out = (float*)d_out;

    int nx    = in_sizes[0];
    int nrows = nx / DDIM;
    int K     = in_sizes[1] / DDIM;

    cudaFuncSetAttribute(argmin_mma, cudaFuncAttributeMaxDynamicSharedMemorySize, SMEM_BYTES);

    prep_kernel<<<K, 128>>>(cb, K);
    argmin_mma<<<(nrows + 127) / 128, 512, SMEM_BYTES>>>(x, nrows, K);
    rescore_gather_kernel<<<(nrows + 7) / 8, 256>>>(x, cb, out, nrows);
    finalize_kernel<<<1, 256>>>(out, (long long)nx, nrows, K);
}